// round 11
// baseline (speedup 1.0000x reference)
#include <cuda_runtime.h>
#include <cuda_fp16.h>
#include <cstdint>
#include <math.h>

#define BB   1024
#define SEQ  65
#define CC   1024
#define HH   16
#define HID  4096
#define MTOT (BB*SEQ)   // 66560 = 520 * 128

// ---------------- scratch (device globals: no allocations allowed) ----------
__device__ __half g_h  [(size_t)MTOT * CC];      // LN output (fp16)
__device__ __half g_qkv[(size_t)MTOT * 3 * CC];  // QKV output (fp16)
__device__ __half g_att[(size_t)MTOT * CC];      // attention output (fp16)
__device__ __half g_act[(size_t)MTOT * HID];     // gelu(fc1) (fp16)
__device__ __half g_wq [(size_t)3 * CC * CC];    // fp16 weights
__device__ __half g_wp [(size_t)CC * CC];
__device__ __half g_w1 [(size_t)HID * CC];
__device__ __half g_w2 [(size_t)CC * HID];

// ---------------- helpers ---------------------------------------------------
__device__ __forceinline__ void mma_f16(float c[4], const uint32_t a[4], const uint32_t b[2]) {
    asm volatile(
        "mma.sync.aligned.m16n8k16.row.col.f32.f16.f16.f32 "
        "{%0,%1,%2,%3}, {%4,%5,%6,%7}, {%8,%9}, {%0,%1,%2,%3};\n"
        : "+f"(c[0]), "+f"(c[1]), "+f"(c[2]), "+f"(c[3])
        : "r"(a[0]), "r"(a[1]), "r"(a[2]), "r"(a[3]), "r"(b[0]), "r"(b[1]));
}

__device__ __forceinline__ void ldsm4(uint32_t r[4], uint32_t addr) {
    asm volatile("ldmatrix.sync.aligned.m8n8.x4.shared.b16 {%0,%1,%2,%3}, [%4];"
        : "=r"(r[0]), "=r"(r[1]), "=r"(r[2]), "=r"(r[3]) : "r"(addr));
}

__device__ __forceinline__ void ldsm4t(uint32_t r[4], uint32_t addr) {
    asm volatile("ldmatrix.sync.aligned.m8n8.x4.trans.shared.b16 {%0,%1,%2,%3}, [%4];"
        : "=r"(r[0]), "=r"(r[1]), "=r"(r[2]), "=r"(r[3]) : "r"(addr));
}

__device__ __forceinline__ float gelu_tanh(float x) {
    float x3 = x * x * x;
    return 0.5f * x * (1.0f + tanhf(0.7978845608028654f * (x + 0.044715f * x3)));
}

__device__ __forceinline__ uint32_t smem_u32(const void* p) {
    uint32_t a;
    asm("{ .reg .u64 t; cvta.to.shared.u64 t, %1; cvt.u32.u64 %0, t; }" : "=r"(a) : "l"(p));
    return a;
}

__device__ __forceinline__ void cpasync16(uint32_t dst, const void* src) {
    asm volatile("cp.async.cg.shared.global [%0], [%1], 16;" :: "r"(dst), "l"(src));
}

// ---------------- fp32 -> fp16 conversion of ALL weights, one launch --------
#define NW_Q (3 * CC * CC / 2)
#define NW_P (CC * CC / 2)
#define NW_1 (HID * CC / 2)
#define NW_2 (CC * HID / 2)
#define NW_TOT (NW_Q + NW_P + NW_1 + NW_2)

__global__ __launch_bounds__(256)
void conv_all(const float2* __restrict__ sq, const float2* __restrict__ sp,
              const float2* __restrict__ s1, const float2* __restrict__ s2,
              __half2* __restrict__ dq, __half2* __restrict__ dp,
              __half2* __restrict__ d1, __half2* __restrict__ d2) {
    int i = blockIdx.x * blockDim.x + threadIdx.x;
    int stride = gridDim.x * blockDim.x;
    for (; i < NW_TOT; i += stride) {
        const float2* s; __half2* d; int off;
        if (i < NW_Q)                   { s = sq; d = dq; off = i; }
        else if (i < NW_Q + NW_P)       { s = sp; d = dp; off = i - NW_Q; }
        else if (i < NW_Q + NW_P + NW_1){ s = s1; d = d1; off = i - NW_Q - NW_P; }
        else                            { s = s2; d = d2; off = i - NW_Q - NW_P - NW_1; }
        float2 v = s[off];
        d[off] = __floats2half2_rn(v.x, v.y);
    }
}

// ---------------- LayerNorm (fp16 output) ------------------------------------
__global__ __launch_bounds__(256)
void ln_kernel(const float* __restrict__ x, const float* __restrict__ g,
               const float* __restrict__ b, __half* __restrict__ y) {
    int row = blockIdx.x;
    const float4* xr = (const float4*)(x + (size_t)row * CC);
    float4 v = xr[threadIdx.x];
    float s1 = v.x + v.y + v.z + v.w;
    float s2 = v.x * v.x + v.y * v.y + v.z * v.z + v.w * v.w;
    #pragma unroll
    for (int o = 16; o; o >>= 1) {
        s1 += __shfl_xor_sync(0xffffffffu, s1, o);
        s2 += __shfl_xor_sync(0xffffffffu, s2, o);
    }
    __shared__ float r1[8], r2[8];
    int w = threadIdx.x >> 5;
    if ((threadIdx.x & 31) == 0) { r1[w] = s1; r2[w] = s2; }
    __syncthreads();
    s1 = 0.f; s2 = 0.f;
    #pragma unroll
    for (int i = 0; i < 8; i++) { s1 += r1[i]; s2 += r2[i]; }
    float mu  = s1 * (1.0f / CC);
    float var = s2 * (1.0f / CC) - mu * mu;
    float rs  = rsqrtf(var + 1e-5f);
    float4 gv = ((const float4*)g)[threadIdx.x];
    float4 bv = ((const float4*)b)[threadIdx.x];
    __half2* yr = (__half2*)(y + (size_t)row * CC);
    yr[2 * threadIdx.x + 0] = __floats2half2_rn((v.x - mu) * rs * gv.x + bv.x,
                                                (v.y - mu) * rs * gv.y + bv.y);
    yr[2 * threadIdx.x + 1] = __floats2half2_rn((v.z - mu) * rs * gv.z + bv.z,
                                                (v.w - mu) * rs * gv.w + bv.w);
}

// ---------------- FP16 mma.sync GEMM (byte-exact round-7 config) ------------
enum { EPI_BIAS = 0, EPI_RES = 1, EPI_GELU = 2 };

#define KCH         64
#define STAGE_BYTES 32768
#define NSTAGE      3
#define GSMEM_TOTAL (NSTAGE * STAGE_BYTES)

template <int EPI, typename OT>
__global__ __launch_bounds__(128, 2)
void gemm_f16(const __half* __restrict__ A, const __half* __restrict__ W,
              const float* __restrict__ bias, const float* __restrict__ res,
              OT* __restrict__ out, int K, int N) {
    extern __shared__ __align__(256) char smem_raw[];
    uint32_t sbase = smem_u32(smem_raw);

    int tid = threadIdx.x, w = tid >> 5, lane = tid & 31;
    int g = lane >> 2, t = lane & 3;
    int bm = blockIdx.y * 128, bn = blockIdx.x * 128;
    int wm = (w & 1) * 64, wn = (w >> 1) * 64;

    int j    = lane & 7;
    int bsel = lane >> 3;
    int rowA = wm + (bsel & 1) * 8 + j;
    int cA0  = bsel >> 1;
    int rowB = wn + (bsel >> 1) * 8 + j;
    int cB0  = bsel & 1;

    const int nk = K / KCH;

    auto load_stage = [&](int s, int k0) {
        uint32_t sb = sbase + s * STAGE_BYTES;
        #pragma unroll
        for (int i = 0; i < 16; i++) {
            int c = tid + 128 * i;
            int row = c >> 3, ch = c & 7;
            const __half* src = (row < 128)
                ? (A + (size_t)(bm + row) * K + k0 + ch * 8)
                : (W + (size_t)(bn + row - 128) * K + k0 + ch * 8);
            cpasync16(sb + row * 128 + 16 * (ch ^ (row & 7)), src);
        }
        asm volatile("cp.async.commit_group;" ::: "memory");
    };

    float acc[4][8][4];
    #pragma unroll
    for (int mt = 0; mt < 4; mt++)
        #pragma unroll
        for (int nt = 0; nt < 8; nt++)
            #pragma unroll
            for (int q = 0; q < 4; q++) acc[mt][nt][q] = 0.f;

    load_stage(0, 0);
    load_stage(1, KCH);

    for (int kt = 0; kt < nk; kt++) {
        asm volatile("cp.async.wait_group 1;" ::: "memory");  // stage kt ready
        __syncthreads();
        if (kt + 2 < nk) load_stage((kt + 2) % NSTAGE, (kt + 2) * KCH);
        else { asm volatile("cp.async.commit_group;" ::: "memory"); }

        uint32_t Asm = sbase + (kt % NSTAGE) * STAGE_BYTES;
        uint32_t Bsm = Asm + 16384;

        #pragma unroll
        for (int kb = 0; kb < 4; kb++) {
            uint32_t af[4][4];
            #pragma unroll
            for (int mt = 0; mt < 4; mt++) {
                int r = rowA + mt * 16;
                ldsm4(af[mt], Asm + r * 128 + 16 * ((2 * kb + cA0) ^ (r & 7)));
            }
            uint32_t bf[8][2];
            #pragma unroll
            for (int p = 0; p < 4; p++) {
                int n = rowB + p * 16;
                uint32_t tmp[4];
                ldsm4(tmp, Bsm + n * 128 + 16 * ((2 * kb + cB0) ^ (n & 7)));
                bf[2 * p][0]     = tmp[0]; bf[2 * p][1]     = tmp[1];
                bf[2 * p + 1][0] = tmp[2]; bf[2 * p + 1][1] = tmp[3];
            }
            #pragma unroll
            for (int mt = 0; mt < 4; mt++)
                #pragma unroll
                for (int nt = 0; nt < 8; nt++)
                    mma_f16(acc[mt][nt], af[mt], bf[nt]);
        }
        // stage (kt%3) reread-safe: next overwrite happens after iter kt+1's
        // top-of-loop barrier, which follows all reads here.
    }

    #pragma unroll
    for (int mt = 0; mt < 4; mt++) {
        #pragma unroll
        for (int nt = 0; nt < 8; nt++) {
            int rr0 = bm + wm + mt * 16 + g;
            int cc  = bn + wn + nt * 8 + 2 * t;
            float b0 = bias[cc], b1 = bias[cc + 1];
            #pragma unroll
            for (int hh = 0; hh < 2; hh++) {
                int rr = rr0 + hh * 8;
                float v0 = acc[mt][nt][hh * 2 + 0] + b0;
                float v1 = acc[mt][nt][hh * 2 + 1] + b1;
                if (EPI == EPI_RES) {
                    float2 rv = *(const float2*)(res + (size_t)rr * N + cc);
                    v0 += rv.x; v1 += rv.y;
                }
                if (EPI == EPI_GELU) {
                    v0 = gelu_tanh(v0);
                    v1 = gelu_tanh(v1);
                }
                OT* dst = out + (size_t)rr * N + cc;
                if (sizeof(OT) == 2) {
                    *(__half2*)dst = __floats2half2_rn(v0, v1);
                } else {
                    *(float2*)dst = make_float2(v0, v1);
                }
            }
        }
    }
}

// ---------------- Attention: fp16 mma flash-style ---------------------------
// Round-7 algorithm; smem overlay: Q and P share one buffer (sQP, 176B row
// stride). Q stored UNSWIZZLED in the first 128B of each 176B row — ldsm row
// banks 12j mod 32 are all distinct, conflict-free (same property P loads use).
// Safe without extra sync: for every row r, the Q-read (qa regs), P-write and
// P-read all belong to the same warp (warp w owns rows [16w,16w+16)), and the
// Q-read precedes the P-write in that warp's program order.
// smem: 10240(K) + 10240(V) + 14080(QP) = 33.75KB -> 5 blocks/SM (was 4).
__global__ __launch_bounds__(160)
void attn_mma(const __half* __restrict__ qkv, const float* __restrict__ abias,
              const float* __restrict__ bscale_p, __half* __restrict__ out) {
    __shared__ __align__(16) __half sK [80 * 64];
    __shared__ __align__(16) __half sV [80 * 64];
    __shared__ __align__(16) __half sQP[80 * 88];   // Q (first 64 cols), then P

    int bh = blockIdx.x, b = bh >> 4, h = bh & 15;
    int tid = threadIdx.x, w = tid >> 5, lane = tid & 31;
    int g = lane >> 2, t = lane & 3;
    size_t base = (size_t)b * SEQ * 3072 + (size_t)h * 64;

    // load Q (unswizzled, stride 88 halfs) and K,V (XOR-swizzled 128B rows)
    for (int idx = tid; idx < 3 * 640; idx += 160) {
        int m = idx / 640, rem = idx - m * 640;
        int row = rem >> 3, ch = rem & 7;
        uint4 v = make_uint4(0, 0, 0, 0);
        if (row < SEQ)
            v = *(const uint4*)(qkv + base + (size_t)row * 3072 + m * 1024 + ch * 8);
        if (m == 0) {
            *(uint4*)(sQP + row * 88 + ch * 8) = v;
        } else {
            __half* dst = (m == 1) ? sK : sV;
            *(uint4*)(dst + row * 64 + ((ch ^ (row & 7)) * 8)) = v;
        }
    }
    __syncthreads();

    float bsc = *bscale_p;
    uint32_t sKb = smem_u32(sK), sVb = smem_u32(sV), sQPb = smem_u32(sQP);

    int j = lane & 7, bsel = lane >> 3;
    int mt = w;

    // ---- Q fragments (consume sQP rows before P overwrites them) ----
    int rowA = mt * 16 + (bsel & 1) * 8 + j;
    int cA0  = bsel >> 1;
    uint32_t qa[4][4];
    #pragma unroll
    for (int kt = 0; kt < 4; kt++)
        ldsm4(qa[kt], sQPb + rowA * 176 + 16 * (2 * kt + cA0));

    // ---- S = Q @ K^T ----
    float sacc[10][4];
    #pragma unroll
    for (int nt = 0; nt < 10; nt++)
        #pragma unroll
        for (int q = 0; q < 4; q++) sacc[nt][q] = 0.f;

    int rowKb = (bsel >> 1) * 8 + j;
    int cB0   = bsel & 1;
    #pragma unroll
    for (int nb = 0; nb < 5; nb++) {
        int rK = nb * 16 + rowKb;
        #pragma unroll
        for (int kt = 0; kt < 4; kt++) {
            uint32_t tmp[4];
            ldsm4(tmp, sKb + rK * 128 + 16 * ((2 * kt + cB0) ^ (rK & 7)));
            uint32_t bf0[2] = {tmp[0], tmp[1]}, bf1[2] = {tmp[2], tmp[3]};
            mma_f16(sacc[2 * nb],     qa[kt], bf0);
            mma_f16(sacc[2 * nb + 1], qa[kt], bf1);
        }
    }

    // ---- softmax rows, write P (fp16) into sQP ----
    #pragma unroll
    for (int hr = 0; hr < 2; hr++) {
        int r = mt * 16 + g + 8 * hr;
        int rc = (r < SEQ) ? r : (SEQ - 1);
        const float* brow = abias + ((size_t)h * SEQ + rc) * SEQ;
        float l[20];
        float mx = -1e30f;
        #pragma unroll
        for (int nt = 0; nt < 10; nt++) {
            #pragma unroll
            for (int e = 0; e < 2; e++) {
                int c = 8 * nt + 2 * t + e;
                float lv = -1e30f;
                if (r < SEQ && c < SEQ)
                    lv = sacc[nt][2 * hr + e] * 0.125f + bsc * brow[c];
                l[nt * 2 + e] = lv;
                mx = fmaxf(mx, lv);
            }
        }
        mx = fmaxf(mx, __shfl_xor_sync(0xffffffffu, mx, 1));
        mx = fmaxf(mx, __shfl_xor_sync(0xffffffffu, mx, 2));
        float s = 0.f;
        #pragma unroll
        for (int i = 0; i < 20; i++) { l[i] = __expf(l[i] - mx); s += l[i]; }
        s += __shfl_xor_sync(0xffffffffu, s, 1);
        s += __shfl_xor_sync(0xffffffffu, s, 2);
        float inv = 1.0f / s;
        #pragma unroll
        for (int nt = 0; nt < 10; nt++)
            *(__half2*)(sQP + r * 88 + 8 * nt + 2 * t) =
                __floats2half2_rn(l[2 * nt] * inv, l[2 * nt + 1] * inv);
    }
    __syncwarp();

    // ---- O = P @ V ----
    float oacc[8][4];
    #pragma unroll
    for (int nt = 0; nt < 8; nt++)
        #pragma unroll
        for (int q = 0; q < 4; q++) oacc[nt][q] = 0.f;

    int rowP = mt * 16 + (bsel & 1) * 8 + j;
    int kl   = lane & 15;
    int ctop = lane >> 4;
    #pragma unroll
    for (int kt = 0; kt < 5; kt++) {
        uint32_t pa[4];
        ldsm4(pa, sQPb + rowP * 176 + 16 * (2 * kt + (bsel >> 1)));
        int krow = kt * 16 + kl;
        #pragma unroll
        for (int nb2 = 0; nb2 < 4; nb2++) {
            uint32_t tmp[4];
            int col8 = 2 * nb2 + ctop;
            ldsm4t(tmp, sVb + krow * 128 + 16 * (col8 ^ (krow & 7)));
            uint32_t bf0[2] = {tmp[0], tmp[1]}, bf1[2] = {tmp[2], tmp[3]};
            mma_f16(oacc[2 * nb2],     pa, bf0);
            mma_f16(oacc[2 * nb2 + 1], pa, bf1);
        }
    }

    size_t ob = (size_t)b * SEQ * 1024 + (size_t)h * 64;
    #pragma unroll
    for (int hr = 0; hr < 2; hr++) {
        int r = mt * 16 + g + 8 * hr;
        if (r < SEQ) {
            #pragma unroll
            for (int nt = 0; nt < 8; nt++)
                *(__half2*)(out + ob + (size_t)r * 1024 + 8 * nt + 2 * t) =
                    __floats2half2_rn(oacc[nt][2 * hr], oacc[nt][2 * hr + 1]);
        }
    }
}

// ---------------- launch -----------------------------------------------------
extern "C" void kernel_launch(void* const* d_in, const int* in_sizes, int n_in,
                              void* d_out, int out_size) {
    const float* x        = (const float*)d_in[0];
    const float* ln1_g    = (const float*)d_in[1];
    const float* ln1_b    = (const float*)d_in[2];
    const float* qkv_w    = (const float*)d_in[3];
    const float* qkv_b    = (const float*)d_in[4];
    const float* proj_w   = (const float*)d_in[5];
    const float* proj_b   = (const float*)d_in[6];
    const float* attnbias = (const float*)d_in[7];
    const float* bscale   = (const float*)d_in[8];
    const float* ln2_g    = (const float*)d_in[9];
    const float* ln2_b    = (const float*)d_in[10];
    const float* fc1_w    = (const float*)d_in[11];
    const float* fc1_b    = (const float*)d_in[12];
    const float* fc2_w    = (const float*)d_in[13];
    const float* fc2_b    = (const float*)d_in[14];
    float* out = (float*)d_out;

    __half *h, *qkv, *att, *act, *wq, *wp, *w1, *w2;
    cudaGetSymbolAddress((void**)&h,   g_h);
    cudaGetSymbolAddress((void**)&qkv, g_qkv);
    cudaGetSymbolAddress((void**)&att, g_att);
    cudaGetSymbolAddress((void**)&act, g_act);
    cudaGetSymbolAddress((void**)&wq,  g_wq);
    cudaGetSymbolAddress((void**)&wp,  g_wp);
    cudaGetSymbolAddress((void**)&w1,  g_w1);
    cudaGetSymbolAddress((void**)&w2,  g_w2);

    cudaFuncSetAttribute((const void*)gemm_f16<EPI_BIAS, __half>,
                         cudaFuncAttributeMaxDynamicSharedMemorySize, GSMEM_TOTAL);
    cudaFuncSetAttribute((const void*)gemm_f16<EPI_RES, float>,
                         cudaFuncAttributeMaxDynamicSharedMemorySize, GSMEM_TOTAL);
    cudaFuncSetAttribute((const void*)gemm_f16<EPI_GELU, __half>,
                         cudaFuncAttributeMaxDynamicSharedMemorySize, GSMEM_TOTAL);

    // 0. fp16 weights (single launch)
    conv_all<<<1024, 256>>>((const float2*)qkv_w, (const float2*)proj_w,
                            (const float2*)fc1_w, (const float2*)fc2_w,
                            (__half2*)wq, (__half2*)wp, (__half2*)w1, (__half2*)w2);

    // 1. h = LN1(x)   (fp16)
    ln_kernel<<<MTOT, 256>>>(x, ln1_g, ln1_b, h);
    // 2. qkv = h @ qkv_w^T + qkv_b  (fp16 out)
    gemm_f16<EPI_BIAS, __half><<<dim3(3 * CC / 128, MTOT / 128), 128, GSMEM_TOTAL>>>(
        h, wq, qkv_b, nullptr, qkv, CC, 3 * CC);
    // 3. attention -> att (fp16), tensor-core path
    attn_mma<<<BB * HH, 160>>>(qkv, attnbias, bscale, att);
    // 4. out = x + att @ proj_w^T + proj_b  (fp32 out)
    gemm_f16<EPI_RES, float><<<dim3(CC / 128, MTOT / 128), 128, GSMEM_TOTAL>>>(
        att, wp, proj_b, x, out, CC, CC);
    // 5. h = LN2(out)  (fp16)
    ln_kernel<<<MTOT, 256>>>(out, ln2_g, ln2_b, h);
    // 6. act = gelu(h @ fc1_w^T + fc1_b)  (fp16)
    gemm_f16<EPI_GELU, __half><<<dim3(HID / 128, MTOT / 128), 128, GSMEM_TOTAL>>>(
        h, w1, fc1_b, nullptr, act, CC, HID);
    // 7. out = out + act @ fc2_w^T + fc2_b  (fp32 out)
    gemm_f16<EPI_RES, float><<<dim3(CC / 128, MTOT / 128), 128, GSMEM_TOTAL>>>(
        act, w2, fc2_b, out, out, HID, CC);
}

// round 12
// speedup vs baseline: 1.0132x; 1.0132x over previous
#include <cuda_runtime.h>
#include <cuda_fp16.h>
#include <cstdint>
#include <math.h>

#define BB   1024
#define SEQ  65
#define CC   1024
#define HH   16
#define HID  4096
#define MTOT (BB*SEQ)   // 66560 = 520 * 128

// ---------------- scratch (device globals: no allocations allowed) ----------
__device__ __half g_h  [(size_t)MTOT * CC];      // LN output (fp16)
__device__ __half g_qkv[(size_t)MTOT * 3 * CC];  // QKV output (fp16)
__device__ __half g_att[(size_t)MTOT * CC];      // attention output (fp16)
__device__ __half g_act[(size_t)MTOT * HID];     // gelu(fc1) (fp16)
__device__ __half g_wq [(size_t)3 * CC * CC];    // fp16 weights
__device__ __half g_wp [(size_t)CC * CC];
__device__ __half g_w1 [(size_t)HID * CC];
__device__ __half g_w2 [(size_t)CC * HID];

// ---------------- helpers ---------------------------------------------------
__device__ __forceinline__ void mma_f16(float c[4], const uint32_t a[4], const uint32_t b[2]) {
    asm volatile(
        "mma.sync.aligned.m16n8k16.row.col.f32.f16.f16.f32 "
        "{%0,%1,%2,%3}, {%4,%5,%6,%7}, {%8,%9}, {%0,%1,%2,%3};\n"
        : "+f"(c[0]), "+f"(c[1]), "+f"(c[2]), "+f"(c[3])
        : "r"(a[0]), "r"(a[1]), "r"(a[2]), "r"(a[3]), "r"(b[0]), "r"(b[1]));
}

__device__ __forceinline__ void ldsm4(uint32_t r[4], uint32_t addr) {
    asm volatile("ldmatrix.sync.aligned.m8n8.x4.shared.b16 {%0,%1,%2,%3}, [%4];"
        : "=r"(r[0]), "=r"(r[1]), "=r"(r[2]), "=r"(r[3]) : "r"(addr));
}

__device__ __forceinline__ void ldsm4t(uint32_t r[4], uint32_t addr) {
    asm volatile("ldmatrix.sync.aligned.m8n8.x4.trans.shared.b16 {%0,%1,%2,%3}, [%4];"
        : "=r"(r[0]), "=r"(r[1]), "=r"(r[2]), "=r"(r[3]) : "r"(addr));
}

__device__ __forceinline__ float gelu_tanh(float x) {
    float x3 = x * x * x;
    return 0.5f * x * (1.0f + tanhf(0.7978845608028654f * (x + 0.044715f * x3)));
}

__device__ __forceinline__ uint32_t smem_u32(const void* p) {
    uint32_t a;
    asm("{ .reg .u64 t; cvta.to.shared.u64 t, %1; cvt.u32.u64 %0, t; }" : "=r"(a) : "l"(p));
    return a;
}

__device__ __forceinline__ void cpasync16(uint32_t dst, const void* src) {
    asm volatile("cp.async.cg.shared.global [%0], [%1], 16;" :: "r"(dst), "l"(src));
}

// ---------------- fp32 -> fp16 conversion of ALL weights, one launch --------
#define NW_Q (3 * CC * CC / 2)
#define NW_P (CC * CC / 2)
#define NW_1 (HID * CC / 2)
#define NW_2 (CC * HID / 2)
#define NW_TOT (NW_Q + NW_P + NW_1 + NW_2)

__global__ __launch_bounds__(256)
void conv_all(const float2* __restrict__ sq, const float2* __restrict__ sp,
              const float2* __restrict__ s1, const float2* __restrict__ s2,
              __half2* __restrict__ dq, __half2* __restrict__ dp,
              __half2* __restrict__ d1, __half2* __restrict__ d2) {
    int i = blockIdx.x * blockDim.x + threadIdx.x;
    int stride = gridDim.x * blockDim.x;
    for (; i < NW_TOT; i += stride) {
        const float2* s; __half2* d; int off;
        if (i < NW_Q)                   { s = sq; d = dq; off = i; }
        else if (i < NW_Q + NW_P)       { s = sp; d = dp; off = i - NW_Q; }
        else if (i < NW_Q + NW_P + NW_1){ s = s1; d = d1; off = i - NW_Q - NW_P; }
        else                            { s = s2; d = d2; off = i - NW_Q - NW_P - NW_1; }
        float2 v = s[off];
        d[off] = __floats2half2_rn(v.x, v.y);
    }
}

// ---------------- LayerNorm (fp16 output) ------------------------------------
__global__ __launch_bounds__(256)
void ln_kernel(const float* __restrict__ x, const float* __restrict__ g,
               const float* __restrict__ b, __half* __restrict__ y) {
    int row = blockIdx.x;
    const float4* xr = (const float4*)(x + (size_t)row * CC);
    float4 v = xr[threadIdx.x];
    float s1 = v.x + v.y + v.z + v.w;
    float s2 = v.x * v.x + v.y * v.y + v.z * v.z + v.w * v.w;
    #pragma unroll
    for (int o = 16; o; o >>= 1) {
        s1 += __shfl_xor_sync(0xffffffffu, s1, o);
        s2 += __shfl_xor_sync(0xffffffffu, s2, o);
    }
    __shared__ float r1[8], r2[8];
    int w = threadIdx.x >> 5;
    if ((threadIdx.x & 31) == 0) { r1[w] = s1; r2[w] = s2; }
    __syncthreads();
    s1 = 0.f; s2 = 0.f;
    #pragma unroll
    for (int i = 0; i < 8; i++) { s1 += r1[i]; s2 += r2[i]; }
    float mu  = s1 * (1.0f / CC);
    float var = s2 * (1.0f / CC) - mu * mu;
    float rs  = rsqrtf(var + 1e-5f);
    float4 gv = ((const float4*)g)[threadIdx.x];
    float4 bv = ((const float4*)b)[threadIdx.x];
    __half2* yr = (__half2*)(y + (size_t)row * CC);
    yr[2 * threadIdx.x + 0] = __floats2half2_rn((v.x - mu) * rs * gv.x + bv.x,
                                                (v.y - mu) * rs * gv.y + bv.y);
    yr[2 * threadIdx.x + 1] = __floats2half2_rn((v.z - mu) * rs * gv.z + bv.z,
                                                (v.w - mu) * rs * gv.w + bv.w);
}

// ---------------- FP16 mma.sync GEMM (byte-exact round-7 config) ------------
enum { EPI_BIAS = 0, EPI_RES = 1, EPI_GELU = 2 };

#define KCH         64
#define STAGE_BYTES 32768
#define NSTAGE      3
#define GSMEM_TOTAL (NSTAGE * STAGE_BYTES)

template <int EPI, typename OT>
__global__ __launch_bounds__(128, 2)
void gemm_f16(const __half* __restrict__ A, const __half* __restrict__ W,
              const float* __restrict__ bias, const float* __restrict__ res,
              OT* __restrict__ out, int K, int N) {
    extern __shared__ __align__(256) char smem_raw[];
    uint32_t sbase = smem_u32(smem_raw);

    int tid = threadIdx.x, w = tid >> 5, lane = tid & 31;
    int g = lane >> 2, t = lane & 3;
    int bm = blockIdx.y * 128, bn = blockIdx.x * 128;
    int wm = (w & 1) * 64, wn = (w >> 1) * 64;

    int j    = lane & 7;
    int bsel = lane >> 3;
    int rowA = wm + (bsel & 1) * 8 + j;
    int cA0  = bsel >> 1;
    int rowB = wn + (bsel >> 1) * 8 + j;
    int cB0  = bsel & 1;

    const int nk = K / KCH;

    auto load_stage = [&](int s, int k0) {
        uint32_t sb = sbase + s * STAGE_BYTES;
        #pragma unroll
        for (int i = 0; i < 16; i++) {
            int c = tid + 128 * i;
            int row = c >> 3, ch = c & 7;
            const __half* src = (row < 128)
                ? (A + (size_t)(bm + row) * K + k0 + ch * 8)
                : (W + (size_t)(bn + row - 128) * K + k0 + ch * 8);
            cpasync16(sb + row * 128 + 16 * (ch ^ (row & 7)), src);
        }
        asm volatile("cp.async.commit_group;" ::: "memory");
    };

    float acc[4][8][4];
    #pragma unroll
    for (int mt = 0; mt < 4; mt++)
        #pragma unroll
        for (int nt = 0; nt < 8; nt++)
            #pragma unroll
            for (int q = 0; q < 4; q++) acc[mt][nt][q] = 0.f;

    load_stage(0, 0);
    load_stage(1, KCH);

    for (int kt = 0; kt < nk; kt++) {
        asm volatile("cp.async.wait_group 1;" ::: "memory");  // stage kt ready
        __syncthreads();
        if (kt + 2 < nk) load_stage((kt + 2) % NSTAGE, (kt + 2) * KCH);
        else { asm volatile("cp.async.commit_group;" ::: "memory"); }

        uint32_t Asm = sbase + (kt % NSTAGE) * STAGE_BYTES;
        uint32_t Bsm = Asm + 16384;

        #pragma unroll
        for (int kb = 0; kb < 4; kb++) {
            uint32_t af[4][4];
            #pragma unroll
            for (int mt = 0; mt < 4; mt++) {
                int r = rowA + mt * 16;
                ldsm4(af[mt], Asm + r * 128 + 16 * ((2 * kb + cA0) ^ (r & 7)));
            }
            uint32_t bf[8][2];
            #pragma unroll
            for (int p = 0; p < 4; p++) {
                int n = rowB + p * 16;
                uint32_t tmp[4];
                ldsm4(tmp, Bsm + n * 128 + 16 * ((2 * kb + cB0) ^ (n & 7)));
                bf[2 * p][0]     = tmp[0]; bf[2 * p][1]     = tmp[1];
                bf[2 * p + 1][0] = tmp[2]; bf[2 * p + 1][1] = tmp[3];
            }
            #pragma unroll
            for (int mt = 0; mt < 4; mt++)
                #pragma unroll
                for (int nt = 0; nt < 8; nt++)
                    mma_f16(acc[mt][nt], af[mt], bf[nt]);
        }
        // stage (kt%3) reread-safe: next overwrite happens after iter kt+1's
        // top-of-loop barrier, which follows all reads here.
    }

    #pragma unroll
    for (int mt = 0; mt < 4; mt++) {
        #pragma unroll
        for (int nt = 0; nt < 8; nt++) {
            int rr0 = bm + wm + mt * 16 + g;
            int cc  = bn + wn + nt * 8 + 2 * t;
            float b0 = bias[cc], b1 = bias[cc + 1];
            #pragma unroll
            for (int hh = 0; hh < 2; hh++) {
                int rr = rr0 + hh * 8;
                float v0 = acc[mt][nt][hh * 2 + 0] + b0;
                float v1 = acc[mt][nt][hh * 2 + 1] + b1;
                if (EPI == EPI_RES) {
                    float2 rv = *(const float2*)(res + (size_t)rr * N + cc);
                    v0 += rv.x; v1 += rv.y;
                }
                if (EPI == EPI_GELU) {
                    v0 = gelu_tanh(v0);
                    v1 = gelu_tanh(v1);
                }
                OT* dst = out + (size_t)rr * N + cc;
                if (sizeof(OT) == 2) {
                    *(__half2*)dst = __floats2half2_rn(v0, v1);
                } else {
                    *(float2*)dst = make_float2(v0, v1);
                }
            }
        }
    }
}

// ---------------- Attention: fp16 mma flash-style ---------------------------
// Round-11 layout (Q/P overlay, 33.75KB smem) + __launch_bounds__(160,5):
// registers forced to <=80 so 5 blocks/SM (25 warps) fit the 64K-reg file.
__global__ __launch_bounds__(160, 5)
void attn_mma(const __half* __restrict__ qkv, const float* __restrict__ abias,
              const float* __restrict__ bscale_p, __half* __restrict__ out) {
    __shared__ __align__(16) __half sK [80 * 64];
    __shared__ __align__(16) __half sV [80 * 64];
    __shared__ __align__(16) __half sQP[80 * 88];   // Q (first 64 cols), then P

    int bh = blockIdx.x, b = bh >> 4, h = bh & 15;
    int tid = threadIdx.x, w = tid >> 5, lane = tid & 31;
    int g = lane >> 2, t = lane & 3;
    size_t base = (size_t)b * SEQ * 3072 + (size_t)h * 64;

    // load Q (unswizzled, stride 88 halfs) and K,V (XOR-swizzled 128B rows)
    for (int idx = tid; idx < 3 * 640; idx += 160) {
        int m = idx / 640, rem = idx - m * 640;
        int row = rem >> 3, ch = rem & 7;
        uint4 v = make_uint4(0, 0, 0, 0);
        if (row < SEQ)
            v = *(const uint4*)(qkv + base + (size_t)row * 3072 + m * 1024 + ch * 8);
        if (m == 0) {
            *(uint4*)(sQP + row * 88 + ch * 8) = v;
        } else {
            __half* dst = (m == 1) ? sK : sV;
            *(uint4*)(dst + row * 64 + ((ch ^ (row & 7)) * 8)) = v;
        }
    }
    __syncthreads();

    float bsc = *bscale_p;
    uint32_t sKb = smem_u32(sK), sVb = smem_u32(sV), sQPb = smem_u32(sQP);

    int j = lane & 7, bsel = lane >> 3;
    int mt = w;

    // ---- Q fragments (consume sQP rows before P overwrites them) ----
    int rowA = mt * 16 + (bsel & 1) * 8 + j;
    int cA0  = bsel >> 1;
    uint32_t qa[4][4];
    #pragma unroll
    for (int kt = 0; kt < 4; kt++)
        ldsm4(qa[kt], sQPb + rowA * 176 + 16 * (2 * kt + cA0));

    // ---- S = Q @ K^T ----
    float sacc[10][4];
    #pragma unroll
    for (int nt = 0; nt < 10; nt++)
        #pragma unroll
        for (int q = 0; q < 4; q++) sacc[nt][q] = 0.f;

    int rowKb = (bsel >> 1) * 8 + j;
    int cB0   = bsel & 1;
    #pragma unroll
    for (int nb = 0; nb < 5; nb++) {
        int rK = nb * 16 + rowKb;
        #pragma unroll
        for (int kt = 0; kt < 4; kt++) {
            uint32_t tmp[4];
            ldsm4(tmp, sKb + rK * 128 + 16 * ((2 * kt + cB0) ^ (rK & 7)));
            uint32_t bf0[2] = {tmp[0], tmp[1]}, bf1[2] = {tmp[2], tmp[3]};
            mma_f16(sacc[2 * nb],     qa[kt], bf0);
            mma_f16(sacc[2 * nb + 1], qa[kt], bf1);
        }
    }

    // ---- softmax rows, write P (fp16) into sQP ----
    #pragma unroll
    for (int hr = 0; hr < 2; hr++) {
        int r = mt * 16 + g + 8 * hr;
        int rc = (r < SEQ) ? r : (SEQ - 1);
        const float* brow = abias + ((size_t)h * SEQ + rc) * SEQ;
        float l[20];
        float mx = -1e30f;
        #pragma unroll
        for (int nt = 0; nt < 10; nt++) {
            #pragma unroll
            for (int e = 0; e < 2; e++) {
                int c = 8 * nt + 2 * t + e;
                float lv = -1e30f;
                if (r < SEQ && c < SEQ)
                    lv = sacc[nt][2 * hr + e] * 0.125f + bsc * brow[c];
                l[nt * 2 + e] = lv;
                mx = fmaxf(mx, lv);
            }
        }
        mx = fmaxf(mx, __shfl_xor_sync(0xffffffffu, mx, 1));
        mx = fmaxf(mx, __shfl_xor_sync(0xffffffffu, mx, 2));
        float s = 0.f;
        #pragma unroll
        for (int i = 0; i < 20; i++) { l[i] = __expf(l[i] - mx); s += l[i]; }
        s += __shfl_xor_sync(0xffffffffu, s, 1);
        s += __shfl_xor_sync(0xffffffffu, s, 2);
        float inv = 1.0f / s;
        #pragma unroll
        for (int nt = 0; nt < 10; nt++)
            *(__half2*)(sQP + r * 88 + 8 * nt + 2 * t) =
                __floats2half2_rn(l[2 * nt] * inv, l[2 * nt + 1] * inv);
    }
    __syncwarp();

    // ---- O = P @ V ----
    float oacc[8][4];
    #pragma unroll
    for (int nt = 0; nt < 8; nt++)
        #pragma unroll
        for (int q = 0; q < 4; q++) oacc[nt][q] = 0.f;

    int rowP = mt * 16 + (bsel & 1) * 8 + j;
    int kl   = lane & 15;
    int ctop = lane >> 4;
    #pragma unroll
    for (int kt = 0; kt < 5; kt++) {
        uint32_t pa[4];
        ldsm4(pa, sQPb + rowP * 176 + 16 * (2 * kt + (bsel >> 1)));
        int krow = kt * 16 + kl;
        #pragma unroll
        for (int nb2 = 0; nb2 < 4; nb2++) {
            uint32_t tmp[4];
            int col8 = 2 * nb2 + ctop;
            ldsm4t(tmp, sVb + krow * 128 + 16 * (col8 ^ (krow & 7)));
            uint32_t bf0[2] = {tmp[0], tmp[1]}, bf1[2] = {tmp[2], tmp[3]};
            mma_f16(oacc[2 * nb2],     pa, bf0);
            mma_f16(oacc[2 * nb2 + 1], pa, bf1);
        }
    }

    size_t ob = (size_t)b * SEQ * 1024 + (size_t)h * 64;
    #pragma unroll
    for (int hr = 0; hr < 2; hr++) {
        int r = mt * 16 + g + 8 * hr;
        if (r < SEQ) {
            #pragma unroll
            for (int nt = 0; nt < 8; nt++)
                *(__half2*)(out + ob + (size_t)r * 1024 + 8 * nt + 2 * t) =
                    __floats2half2_rn(oacc[nt][2 * hr], oacc[nt][2 * hr + 1]);
        }
    }
}

// ---------------- launch -----------------------------------------------------
extern "C" void kernel_launch(void* const* d_in, const int* in_sizes, int n_in,
                              void* d_out, int out_size) {
    const float* x        = (const float*)d_in[0];
    const float* ln1_g    = (const float*)d_in[1];
    const float* ln1_b    = (const float*)d_in[2];
    const float* qkv_w    = (const float*)d_in[3];
    const float* qkv_b    = (const float*)d_in[4];
    const float* proj_w   = (const float*)d_in[5];
    const float* proj_b   = (const float*)d_in[6];
    const float* attnbias = (const float*)d_in[7];
    const float* bscale   = (const float*)d_in[8];
    const float* ln2_g    = (const float*)d_in[9];
    const float* ln2_b    = (const float*)d_in[10];
    const float* fc1_w    = (const float*)d_in[11];
    const float* fc1_b    = (const float*)d_in[12];
    const float* fc2_w    = (const float*)d_in[13];
    const float* fc2_b    = (const float*)d_in[14];
    float* out = (float*)d_out;

    __half *h, *qkv, *att, *act, *wq, *wp, *w1, *w2;
    cudaGetSymbolAddress((void**)&h,   g_h);
    cudaGetSymbolAddress((void**)&qkv, g_qkv);
    cudaGetSymbolAddress((void**)&att, g_att);
    cudaGetSymbolAddress((void**)&act, g_act);
    cudaGetSymbolAddress((void**)&wq,  g_wq);
    cudaGetSymbolAddress((void**)&wp,  g_wp);
    cudaGetSymbolAddress((void**)&w1,  g_w1);
    cudaGetSymbolAddress((void**)&w2,  g_w2);

    cudaFuncSetAttribute((const void*)gemm_f16<EPI_BIAS, __half>,
                         cudaFuncAttributeMaxDynamicSharedMemorySize, GSMEM_TOTAL);
    cudaFuncSetAttribute((const void*)gemm_f16<EPI_RES, float>,
                         cudaFuncAttributeMaxDynamicSharedMemorySize, GSMEM_TOTAL);
    cudaFuncSetAttribute((const void*)gemm_f16<EPI_GELU, __half>,
                         cudaFuncAttributeMaxDynamicSharedMemorySize, GSMEM_TOTAL);

    // 0. fp16 weights (single launch)
    conv_all<<<1024, 256>>>((const float2*)qkv_w, (const float2*)proj_w,
                            (const float2*)fc1_w, (const float2*)fc2_w,
                            (__half2*)wq, (__half2*)wp, (__half2*)w1, (__half2*)w2);

    // 1. h = LN1(x)   (fp16)
    ln_kernel<<<MTOT, 256>>>(x, ln1_g, ln1_b, h);
    // 2. qkv = h @ qkv_w^T + qkv_b  (fp16 out)
    gemm_f16<EPI_BIAS, __half><<<dim3(3 * CC / 128, MTOT / 128), 128, GSMEM_TOTAL>>>(
        h, wq, qkv_b, nullptr, qkv, CC, 3 * CC);
    // 3. attention -> att (fp16), tensor-core path
    attn_mma<<<BB * HH, 160>>>(qkv, attnbias, bscale, att);
    // 4. out = x + att @ proj_w^T + proj_b  (fp32 out)
    gemm_f16<EPI_RES, float><<<dim3(CC / 128, MTOT / 128), 128, GSMEM_TOTAL>>>(
        att, wp, proj_b, x, out, CC, CC);
    // 5. h = LN2(out)  (fp16)
    ln_kernel<<<MTOT, 256>>>(out, ln2_g, ln2_b, h);
    // 6. act = gelu(h @ fc1_w^T + fc1_b)  (fp16)
    gemm_f16<EPI_GELU, __half><<<dim3(HID / 128, MTOT / 128), 128, GSMEM_TOTAL>>>(
        h, w1, fc1_b, nullptr, act, CC, HID);
    // 7. out = out + act @ fc2_w^T + fc2_b  (fp32 out)
    gemm_f16<EPI_RES, float><<<dim3(CC / 128, MTOT / 128), 128, GSMEM_TOTAL>>>(
        act, w2, fc2_b, out, out, HID, CC);
}

// round 13
// speedup vs baseline: 1.0185x; 1.0052x over previous
#include <cuda_runtime.h>
#include <cuda_fp16.h>
#include <cstdint>
#include <math.h>

#define BB   1024
#define SEQ  65
#define CC   1024
#define HH   16
#define HID  4096
#define MTOT (BB*SEQ)   // 66560 = 520 * 128

// ---------------- scratch (device globals: no allocations allowed) ----------
__device__ __half g_h  [(size_t)MTOT * CC];      // LN output (fp16)
__device__ __half g_qkv[(size_t)MTOT * 3 * CC];  // QKV output (fp16)
__device__ __half g_att[(size_t)MTOT * CC];      // attention output (fp16)
__device__ __half g_act[(size_t)MTOT * HID];     // gelu(fc1) (fp16)
__device__ __half g_wq [(size_t)3 * CC * CC];    // fp16 weights
__device__ __half g_wp [(size_t)CC * CC];
__device__ __half g_w1 [(size_t)HID * CC];
__device__ __half g_w2 [(size_t)CC * HID];

// ---------------- helpers ---------------------------------------------------
__device__ __forceinline__ void mma_f16(float c[4], const uint32_t a[4], const uint32_t b[2]) {
    asm volatile(
        "mma.sync.aligned.m16n8k16.row.col.f32.f16.f16.f32 "
        "{%0,%1,%2,%3}, {%4,%5,%6,%7}, {%8,%9}, {%0,%1,%2,%3};\n"
        : "+f"(c[0]), "+f"(c[1]), "+f"(c[2]), "+f"(c[3])
        : "r"(a[0]), "r"(a[1]), "r"(a[2]), "r"(a[3]), "r"(b[0]), "r"(b[1]));
}

__device__ __forceinline__ void ldsm4(uint32_t r[4], uint32_t addr) {
    asm volatile("ldmatrix.sync.aligned.m8n8.x4.shared.b16 {%0,%1,%2,%3}, [%4];"
        : "=r"(r[0]), "=r"(r[1]), "=r"(r[2]), "=r"(r[3]) : "r"(addr));
}

__device__ __forceinline__ void ldsm4t(uint32_t r[4], uint32_t addr) {
    asm volatile("ldmatrix.sync.aligned.m8n8.x4.trans.shared.b16 {%0,%1,%2,%3}, [%4];"
        : "=r"(r[0]), "=r"(r[1]), "=r"(r[2]), "=r"(r[3]) : "r"(addr));
}

__device__ __forceinline__ float gelu_tanh(float x) {
    float x3 = x * x * x;
    return 0.5f * x * (1.0f + tanhf(0.7978845608028654f * (x + 0.044715f * x3)));
}

__device__ __forceinline__ uint32_t smem_u32(const void* p) {
    uint32_t a;
    asm("{ .reg .u64 t; cvta.to.shared.u64 t, %1; cvt.u32.u64 %0, t; }" : "=r"(a) : "l"(p));
    return a;
}

__device__ __forceinline__ void cpasync16(uint32_t dst, const void* src) {
    asm volatile("cp.async.cg.shared.global [%0], [%1], 16;" :: "r"(dst), "l"(src));
}

// ---------------- fp32 -> fp16 conversion of ALL weights, one launch --------
#define NW_Q (3 * CC * CC / 2)
#define NW_P (CC * CC / 2)
#define NW_1 (HID * CC / 2)
#define NW_2 (CC * HID / 2)
#define NW_TOT (NW_Q + NW_P + NW_1 + NW_2)

__global__ __launch_bounds__(256)
void conv_all(const float2* __restrict__ sq, const float2* __restrict__ sp,
              const float2* __restrict__ s1, const float2* __restrict__ s2,
              __half2* __restrict__ dq, __half2* __restrict__ dp,
              __half2* __restrict__ d1, __half2* __restrict__ d2) {
    int i = blockIdx.x * blockDim.x + threadIdx.x;
    int stride = gridDim.x * blockDim.x;
    for (; i < NW_TOT; i += stride) {
        const float2* s; __half2* d; int off;
        if (i < NW_Q)                   { s = sq; d = dq; off = i; }
        else if (i < NW_Q + NW_P)       { s = sp; d = dp; off = i - NW_Q; }
        else if (i < NW_Q + NW_P + NW_1){ s = s1; d = d1; off = i - NW_Q - NW_P; }
        else                            { s = s2; d = d2; off = i - NW_Q - NW_P - NW_1; }
        float2 v = s[off];
        d[off] = __floats2half2_rn(v.x, v.y);
    }
}

// ---------------- LayerNorm (fp16 output) ------------------------------------
__global__ __launch_bounds__(256)
void ln_kernel(const float* __restrict__ x, const float* __restrict__ g,
               const float* __restrict__ b, __half* __restrict__ y) {
    int row = blockIdx.x;
    const float4* xr = (const float4*)(x + (size_t)row * CC);
    float4 v = xr[threadIdx.x];
    float s1 = v.x + v.y + v.z + v.w;
    float s2 = v.x * v.x + v.y * v.y + v.z * v.z + v.w * v.w;
    #pragma unroll
    for (int o = 16; o; o >>= 1) {
        s1 += __shfl_xor_sync(0xffffffffu, s1, o);
        s2 += __shfl_xor_sync(0xffffffffu, s2, o);
    }
    __shared__ float r1[8], r2[8];
    int w = threadIdx.x >> 5;
    if ((threadIdx.x & 31) == 0) { r1[w] = s1; r2[w] = s2; }
    __syncthreads();
    s1 = 0.f; s2 = 0.f;
    #pragma unroll
    for (int i = 0; i < 8; i++) { s1 += r1[i]; s2 += r2[i]; }
    float mu  = s1 * (1.0f / CC);
    float var = s2 * (1.0f / CC) - mu * mu;
    float rs  = rsqrtf(var + 1e-5f);
    float4 gv = ((const float4*)g)[threadIdx.x];
    float4 bv = ((const float4*)b)[threadIdx.x];
    __half2* yr = (__half2*)(y + (size_t)row * CC);
    yr[2 * threadIdx.x + 0] = __floats2half2_rn((v.x - mu) * rs * gv.x + bv.x,
                                                (v.y - mu) * rs * gv.y + bv.y);
    yr[2 * threadIdx.x + 1] = __floats2half2_rn((v.z - mu) * rs * gv.z + bv.z,
                                                (v.w - mu) * rs * gv.w + bv.w);
}

// ---------------- FP16 mma.sync GEMM (byte-exact round-7 config) ------------
enum { EPI_BIAS = 0, EPI_RES = 1, EPI_GELU = 2 };

#define KCH         64
#define STAGE_BYTES 32768
#define NSTAGE      3
#define GSMEM_TOTAL (NSTAGE * STAGE_BYTES)

template <int EPI, typename OT>
__global__ __launch_bounds__(128, 2)
void gemm_f16(const __half* __restrict__ A, const __half* __restrict__ W,
              const float* __restrict__ bias, const float* __restrict__ res,
              OT* __restrict__ out, int K, int N) {
    extern __shared__ __align__(256) char smem_raw[];
    uint32_t sbase = smem_u32(smem_raw);

    int tid = threadIdx.x, w = tid >> 5, lane = tid & 31;
    int g = lane >> 2, t = lane & 3;
    int bm = blockIdx.y * 128, bn = blockIdx.x * 128;
    int wm = (w & 1) * 64, wn = (w >> 1) * 64;

    int j    = lane & 7;
    int bsel = lane >> 3;
    int rowA = wm + (bsel & 1) * 8 + j;
    int cA0  = bsel >> 1;
    int rowB = wn + (bsel >> 1) * 8 + j;
    int cB0  = bsel & 1;

    const int nk = K / KCH;

    auto load_stage = [&](int s, int k0) {
        uint32_t sb = sbase + s * STAGE_BYTES;
        #pragma unroll
        for (int i = 0; i < 16; i++) {
            int c = tid + 128 * i;
            int row = c >> 3, ch = c & 7;
            const __half* src = (row < 128)
                ? (A + (size_t)(bm + row) * K + k0 + ch * 8)
                : (W + (size_t)(bn + row - 128) * K + k0 + ch * 8);
            cpasync16(sb + row * 128 + 16 * (ch ^ (row & 7)), src);
        }
        asm volatile("cp.async.commit_group;" ::: "memory");
    };

    float acc[4][8][4];
    #pragma unroll
    for (int mt = 0; mt < 4; mt++)
        #pragma unroll
        for (int nt = 0; nt < 8; nt++)
            #pragma unroll
            for (int q = 0; q < 4; q++) acc[mt][nt][q] = 0.f;

    load_stage(0, 0);
    load_stage(1, KCH);

    for (int kt = 0; kt < nk; kt++) {
        asm volatile("cp.async.wait_group 1;" ::: "memory");  // stage kt ready
        __syncthreads();
        if (kt + 2 < nk) load_stage((kt + 2) % NSTAGE, (kt + 2) * KCH);
        else { asm volatile("cp.async.commit_group;" ::: "memory"); }

        uint32_t Asm = sbase + (kt % NSTAGE) * STAGE_BYTES;
        uint32_t Bsm = Asm + 16384;

        #pragma unroll
        for (int kb = 0; kb < 4; kb++) {
            uint32_t af[4][4];
            #pragma unroll
            for (int mt = 0; mt < 4; mt++) {
                int r = rowA + mt * 16;
                ldsm4(af[mt], Asm + r * 128 + 16 * ((2 * kb + cA0) ^ (r & 7)));
            }
            uint32_t bf[8][2];
            #pragma unroll
            for (int p = 0; p < 4; p++) {
                int n = rowB + p * 16;
                uint32_t tmp[4];
                ldsm4(tmp, Bsm + n * 128 + 16 * ((2 * kb + cB0) ^ (n & 7)));
                bf[2 * p][0]     = tmp[0]; bf[2 * p][1]     = tmp[1];
                bf[2 * p + 1][0] = tmp[2]; bf[2 * p + 1][1] = tmp[3];
            }
            #pragma unroll
            for (int mt = 0; mt < 4; mt++)
                #pragma unroll
                for (int nt = 0; nt < 8; nt++)
                    mma_f16(acc[mt][nt], af[mt], bf[nt]);
        }
        // stage (kt%3) reread-safe: next overwrite happens after iter kt+1's
        // top-of-loop barrier, which follows all reads here.
    }

    #pragma unroll
    for (int mt = 0; mt < 4; mt++) {
        #pragma unroll
        for (int nt = 0; nt < 8; nt++) {
            int rr0 = bm + wm + mt * 16 + g;
            int cc  = bn + wn + nt * 8 + 2 * t;
            float b0 = bias[cc], b1 = bias[cc + 1];
            #pragma unroll
            for (int hh = 0; hh < 2; hh++) {
                int rr = rr0 + hh * 8;
                float v0 = acc[mt][nt][hh * 2 + 0] + b0;
                float v1 = acc[mt][nt][hh * 2 + 1] + b1;
                if (EPI == EPI_RES) {
                    float2 rv = *(const float2*)(res + (size_t)rr * N + cc);
                    v0 += rv.x; v1 += rv.y;
                }
                if (EPI == EPI_GELU) {
                    v0 = gelu_tanh(v0);
                    v1 = gelu_tanh(v1);
                }
                OT* dst = out + (size_t)rr * N + cc;
                if (sizeof(OT) == 2) {
                    *(__half2*)dst = __floats2half2_rn(v0, v1);
                } else {
                    *(float2*)dst = make_float2(v0, v1);
                }
            }
        }
    }
}

// ---------------- Attention: fp16 mma flash-style ---------------------------
// Round-12 layout (Q/P overlay, 33.75KB smem); __launch_bounds__(160,6):
// regs forced to <=68 -> 6 blocks/SM (30 warps). smem 6*33.75KB = 202.5KB OK.
__global__ __launch_bounds__(160, 6)
void attn_mma(const __half* __restrict__ qkv, const float* __restrict__ abias,
              const float* __restrict__ bscale_p, __half* __restrict__ out) {
    __shared__ __align__(16) __half sK [80 * 64];
    __shared__ __align__(16) __half sV [80 * 64];
    __shared__ __align__(16) __half sQP[80 * 88];   // Q (first 64 cols), then P

    int bh = blockIdx.x, b = bh >> 4, h = bh & 15;
    int tid = threadIdx.x, w = tid >> 5, lane = tid & 31;
    int g = lane >> 2, t = lane & 3;
    size_t base = (size_t)b * SEQ * 3072 + (size_t)h * 64;

    // load Q (unswizzled, stride 88 halfs) and K,V (XOR-swizzled 128B rows)
    for (int idx = tid; idx < 3 * 640; idx += 160) {
        int m = idx / 640, rem = idx - m * 640;
        int row = rem >> 3, ch = rem & 7;
        uint4 v = make_uint4(0, 0, 0, 0);
        if (row < SEQ)
            v = *(const uint4*)(qkv + base + (size_t)row * 3072 + m * 1024 + ch * 8);
        if (m == 0) {
            *(uint4*)(sQP + row * 88 + ch * 8) = v;
        } else {
            __half* dst = (m == 1) ? sK : sV;
            *(uint4*)(dst + row * 64 + ((ch ^ (row & 7)) * 8)) = v;
        }
    }
    __syncthreads();

    float bsc = *bscale_p;
    uint32_t sKb = smem_u32(sK), sVb = smem_u32(sV), sQPb = smem_u32(sQP);

    int j = lane & 7, bsel = lane >> 3;
    int mt = w;

    // ---- Q fragments (consume sQP rows before P overwrites them) ----
    int rowA = mt * 16 + (bsel & 1) * 8 + j;
    int cA0  = bsel >> 1;
    uint32_t qa[4][4];
    #pragma unroll
    for (int kt = 0; kt < 4; kt++)
        ldsm4(qa[kt], sQPb + rowA * 176 + 16 * (2 * kt + cA0));

    // ---- S = Q @ K^T ----
    float sacc[10][4];
    #pragma unroll
    for (int nt = 0; nt < 10; nt++)
        #pragma unroll
        for (int q = 0; q < 4; q++) sacc[nt][q] = 0.f;

    int rowKb = (bsel >> 1) * 8 + j;
    int cB0   = bsel & 1;
    #pragma unroll
    for (int nb = 0; nb < 5; nb++) {
        int rK = nb * 16 + rowKb;
        #pragma unroll
        for (int kt = 0; kt < 4; kt++) {
            uint32_t tmp[4];
            ldsm4(tmp, sKb + rK * 128 + 16 * ((2 * kt + cB0) ^ (rK & 7)));
            uint32_t bf0[2] = {tmp[0], tmp[1]}, bf1[2] = {tmp[2], tmp[3]};
            mma_f16(sacc[2 * nb],     qa[kt], bf0);
            mma_f16(sacc[2 * nb + 1], qa[kt], bf1);
        }
    }

    // ---- softmax rows, write P (fp16) into sQP ----
    #pragma unroll
    for (int hr = 0; hr < 2; hr++) {
        int r = mt * 16 + g + 8 * hr;
        int rc = (r < SEQ) ? r : (SEQ - 1);
        const float* brow = abias + ((size_t)h * SEQ + rc) * SEQ;
        float l[20];
        float mx = -1e30f;
        #pragma unroll
        for (int nt = 0; nt < 10; nt++) {
            #pragma unroll
            for (int e = 0; e < 2; e++) {
                int c = 8 * nt + 2 * t + e;
                float lv = -1e30f;
                if (r < SEQ && c < SEQ)
                    lv = sacc[nt][2 * hr + e] * 0.125f + bsc * brow[c];
                l[nt * 2 + e] = lv;
                mx = fmaxf(mx, lv);
            }
        }
        mx = fmaxf(mx, __shfl_xor_sync(0xffffffffu, mx, 1));
        mx = fmaxf(mx, __shfl_xor_sync(0xffffffffu, mx, 2));
        float s = 0.f;
        #pragma unroll
        for (int i = 0; i < 20; i++) { l[i] = __expf(l[i] - mx); s += l[i]; }
        s += __shfl_xor_sync(0xffffffffu, s, 1);
        s += __shfl_xor_sync(0xffffffffu, s, 2);
        float inv = 1.0f / s;
        #pragma unroll
        for (int nt = 0; nt < 10; nt++)
            *(__half2*)(sQP + r * 88 + 8 * nt + 2 * t) =
                __floats2half2_rn(l[2 * nt] * inv, l[2 * nt + 1] * inv);
    }
    __syncwarp();

    // ---- O = P @ V ----
    float oacc[8][4];
    #pragma unroll
    for (int nt = 0; nt < 8; nt++)
        #pragma unroll
        for (int q = 0; q < 4; q++) oacc[nt][q] = 0.f;

    int rowP = mt * 16 + (bsel & 1) * 8 + j;
    int kl   = lane & 15;
    int ctop = lane >> 4;
    #pragma unroll
    for (int kt = 0; kt < 5; kt++) {
        uint32_t pa[4];
        ldsm4(pa, sQPb + rowP * 176 + 16 * (2 * kt + (bsel >> 1)));
        int krow = kt * 16 + kl;
        #pragma unroll
        for (int nb2 = 0; nb2 < 4; nb2++) {
            uint32_t tmp[4];
            int col8 = 2 * nb2 + ctop;
            ldsm4t(tmp, sVb + krow * 128 + 16 * (col8 ^ (krow & 7)));
            uint32_t bf0[2] = {tmp[0], tmp[1]}, bf1[2] = {tmp[2], tmp[3]};
            mma_f16(oacc[2 * nb2],     pa, bf0);
            mma_f16(oacc[2 * nb2 + 1], pa, bf1);
        }
    }

    size_t ob = (size_t)b * SEQ * 1024 + (size_t)h * 64;
    #pragma unroll
    for (int hr = 0; hr < 2; hr++) {
        int r = mt * 16 + g + 8 * hr;
        if (r < SEQ) {
            #pragma unroll
            for (int nt = 0; nt < 8; nt++)
                *(__half2*)(out + ob + (size_t)r * 1024 + 8 * nt + 2 * t) =
                    __floats2half2_rn(oacc[nt][2 * hr], oacc[nt][2 * hr + 1]);
        }
    }
}

// ---------------- launch -----------------------------------------------------
extern "C" void kernel_launch(void* const* d_in, const int* in_sizes, int n_in,
                              void* d_out, int out_size) {
    const float* x        = (const float*)d_in[0];
    const float* ln1_g    = (const float*)d_in[1];
    const float* ln1_b    = (const float*)d_in[2];
    const float* qkv_w    = (const float*)d_in[3];
    const float* qkv_b    = (const float*)d_in[4];
    const float* proj_w   = (const float*)d_in[5];
    const float* proj_b   = (const float*)d_in[6];
    const float* attnbias = (const float*)d_in[7];
    const float* bscale   = (const float*)d_in[8];
    const float* ln2_g    = (const float*)d_in[9];
    const float* ln2_b    = (const float*)d_in[10];
    const float* fc1_w    = (const float*)d_in[11];
    const float* fc1_b    = (const float*)d_in[12];
    const float* fc2_w    = (const float*)d_in[13];
    const float* fc2_b    = (const float*)d_in[14];
    float* out = (float*)d_out;

    __half *h, *qkv, *att, *act, *wq, *wp, *w1, *w2;
    cudaGetSymbolAddress((void**)&h,   g_h);
    cudaGetSymbolAddress((void**)&qkv, g_qkv);
    cudaGetSymbolAddress((void**)&att, g_att);
    cudaGetSymbolAddress((void**)&act, g_act);
    cudaGetSymbolAddress((void**)&wq,  g_wq);
    cudaGetSymbolAddress((void**)&wp,  g_wp);
    cudaGetSymbolAddress((void**)&w1,  g_w1);
    cudaGetSymbolAddress((void**)&w2,  g_w2);

    cudaFuncSetAttribute((const void*)gemm_f16<EPI_BIAS, __half>,
                         cudaFuncAttributeMaxDynamicSharedMemorySize, GSMEM_TOTAL);
    cudaFuncSetAttribute((const void*)gemm_f16<EPI_RES, float>,
                         cudaFuncAttributeMaxDynamicSharedMemorySize, GSMEM_TOTAL);
    cudaFuncSetAttribute((const void*)gemm_f16<EPI_GELU, __half>,
                         cudaFuncAttributeMaxDynamicSharedMemorySize, GSMEM_TOTAL);

    // 0. fp16 weights (single launch)
    conv_all<<<1024, 256>>>((const float2*)qkv_w, (const float2*)proj_w,
                            (const float2*)fc1_w, (const float2*)fc2_w,
                            (__half2*)wq, (__half2*)wp, (__half2*)w1, (__half2*)w2);

    // 1. h = LN1(x)   (fp16)
    ln_kernel<<<MTOT, 256>>>(x, ln1_g, ln1_b, h);
    // 2. qkv = h @ qkv_w^T + qkv_b  (fp16 out)
    gemm_f16<EPI_BIAS, __half><<<dim3(3 * CC / 128, MTOT / 128), 128, GSMEM_TOTAL>>>(
        h, wq, qkv_b, nullptr, qkv, CC, 3 * CC);
    // 3. attention -> att (fp16), tensor-core path
    attn_mma<<<BB * HH, 160>>>(qkv, attnbias, bscale, att);
    // 4. out = x + att @ proj_w^T + proj_b  (fp32 out)
    gemm_f16<EPI_RES, float><<<dim3(CC / 128, MTOT / 128), 128, GSMEM_TOTAL>>>(
        att, wp, proj_b, x, out, CC, CC);
    // 5. h = LN2(out)  (fp16)
    ln_kernel<<<MTOT, 256>>>(out, ln2_g, ln2_b, h);
    // 6. act = gelu(h @ fc1_w^T + fc1_b)  (fp16)
    gemm_f16<EPI_GELU, __half><<<dim3(HID / 128, MTOT / 128), 128, GSMEM_TOTAL>>>(
        h, w1, fc1_b, nullptr, act, CC, HID);
    // 7. out = out + act @ fc2_w^T + fc2_b  (fp32 out)
    gemm_f16<EPI_RES, float><<<dim3(CC / 128, MTOT / 128), 128, GSMEM_TOTAL>>>(
        act, w2, fc2_b, out, out, HID, CC);
}

// round 14
// speedup vs baseline: 1.0315x; 1.0127x over previous
#include <cuda_runtime.h>
#include <cuda_fp16.h>
#include <cstdint>
#include <math.h>

#define BB   1024
#define SEQ  65
#define CC   1024
#define HH   16
#define HID  4096
#define MTOT (BB*SEQ)   // 66560 = 520 * 128

// ---------------- scratch (device globals: no allocations allowed) ----------
__device__ __half g_h  [(size_t)MTOT * CC];      // LN output (fp16)
__device__ __half g_qkv[(size_t)MTOT * 3 * CC];  // QKV output (fp16)
__device__ __half g_att[(size_t)MTOT * CC];      // attention output (fp16)
__device__ __half g_act[(size_t)MTOT * HID];     // gelu(fc1) (fp16)
__device__ __half g_wq [(size_t)3 * CC * CC];    // fp16 weights
__device__ __half g_wp [(size_t)CC * CC];
__device__ __half g_w1 [(size_t)HID * CC];
__device__ __half g_w2 [(size_t)CC * HID];

// ---------------- helpers ---------------------------------------------------
__device__ __forceinline__ void mma_f16(float c[4], const uint32_t a[4], const uint32_t b[2]) {
    asm volatile(
        "mma.sync.aligned.m16n8k16.row.col.f32.f16.f16.f32 "
        "{%0,%1,%2,%3}, {%4,%5,%6,%7}, {%8,%9}, {%0,%1,%2,%3};\n"
        : "+f"(c[0]), "+f"(c[1]), "+f"(c[2]), "+f"(c[3])
        : "r"(a[0]), "r"(a[1]), "r"(a[2]), "r"(a[3]), "r"(b[0]), "r"(b[1]));
}

__device__ __forceinline__ void ldsm4(uint32_t r[4], uint32_t addr) {
    asm volatile("ldmatrix.sync.aligned.m8n8.x4.shared.b16 {%0,%1,%2,%3}, [%4];"
        : "=r"(r[0]), "=r"(r[1]), "=r"(r[2]), "=r"(r[3]) : "r"(addr));
}

__device__ __forceinline__ void ldsm4t(uint32_t r[4], uint32_t addr) {
    asm volatile("ldmatrix.sync.aligned.m8n8.x4.trans.shared.b16 {%0,%1,%2,%3}, [%4];"
        : "=r"(r[0]), "=r"(r[1]), "=r"(r[2]), "=r"(r[3]) : "r"(addr));
}

__device__ __forceinline__ float gelu_tanh(float x) {
    float x3 = x * x * x;
    return 0.5f * x * (1.0f + tanhf(0.7978845608028654f * (x + 0.044715f * x3)));
}

__device__ __forceinline__ uint32_t smem_u32(const void* p) {
    uint32_t a;
    asm("{ .reg .u64 t; cvta.to.shared.u64 t, %1; cvt.u32.u64 %0, t; }" : "=r"(a) : "l"(p));
    return a;
}

__device__ __forceinline__ void cpasync16(uint32_t dst, const void* src) {
    asm volatile("cp.async.cg.shared.global [%0], [%1], 16;" :: "r"(dst), "l"(src));
}

// ---------------- fp32 -> fp16 conversion of ALL weights, one launch --------
#define NW_Q (3 * CC * CC / 2)
#define NW_P (CC * CC / 2)
#define NW_1 (HID * CC / 2)
#define NW_2 (CC * HID / 2)
#define NW_TOT (NW_Q + NW_P + NW_1 + NW_2)

__global__ __launch_bounds__(256)
void conv_all(const float2* __restrict__ sq, const float2* __restrict__ sp,
              const float2* __restrict__ s1, const float2* __restrict__ s2,
              __half2* __restrict__ dq, __half2* __restrict__ dp,
              __half2* __restrict__ d1, __half2* __restrict__ d2) {
    int i = blockIdx.x * blockDim.x + threadIdx.x;
    int stride = gridDim.x * blockDim.x;
    for (; i < NW_TOT; i += stride) {
        const float2* s; __half2* d; int off;
        if (i < NW_Q)                   { s = sq; d = dq; off = i; }
        else if (i < NW_Q + NW_P)       { s = sp; d = dp; off = i - NW_Q; }
        else if (i < NW_Q + NW_P + NW_1){ s = s1; d = d1; off = i - NW_Q - NW_P; }
        else                            { s = s2; d = d2; off = i - NW_Q - NW_P - NW_1; }
        float2 v = s[off];
        d[off] = __floats2half2_rn(v.x, v.y);
    }
}

// ---------------- LayerNorm: one WARP per row, 8 rows/block ------------------
// Pure shfl reduction: no smem, no __syncthreads. Lane l holds float4s
// l, l+32, ..., l+224 of the 256-float4 row (coalesced); MLP=8.
__global__ __launch_bounds__(256)
void ln_kernel(const float* __restrict__ x, const float* __restrict__ g,
               const float* __restrict__ b, __half* __restrict__ y) {
    int wid  = threadIdx.x >> 5;
    int lane = threadIdx.x & 31;
    int row  = blockIdx.x * 8 + wid;

    const float4* xr = (const float4*)(x + (size_t)row * CC);
    float4 v[8];
    #pragma unroll
    for (int i = 0; i < 8; i++) v[i] = xr[lane + 32 * i];

    float s1 = 0.f, s2 = 0.f;
    #pragma unroll
    for (int i = 0; i < 8; i++) {
        s1 += v[i].x + v[i].y + v[i].z + v[i].w;
        s2 += v[i].x * v[i].x + v[i].y * v[i].y + v[i].z * v[i].z + v[i].w * v[i].w;
    }
    #pragma unroll
    for (int o = 16; o; o >>= 1) {
        s1 += __shfl_xor_sync(0xffffffffu, s1, o);
        s2 += __shfl_xor_sync(0xffffffffu, s2, o);
    }
    float mu  = s1 * (1.0f / CC);
    float var = s2 * (1.0f / CC) - mu * mu;
    float rs  = rsqrtf(var + 1e-5f);

    const float4* gr = (const float4*)g;
    const float4* br = (const float4*)b;
    __half2* yr = (__half2*)(y + (size_t)row * CC);
    #pragma unroll
    for (int i = 0; i < 8; i++) {
        int c4 = lane + 32 * i;
        float4 gv = gr[c4];
        float4 bv = br[c4];
        yr[2 * c4 + 0] = __floats2half2_rn((v[i].x - mu) * rs * gv.x + bv.x,
                                           (v[i].y - mu) * rs * gv.y + bv.y);
        yr[2 * c4 + 1] = __floats2half2_rn((v[i].z - mu) * rs * gv.z + bv.z,
                                           (v[i].w - mu) * rs * gv.w + bv.w);
    }
}

// ---------------- FP16 mma.sync GEMM (byte-exact round-7 config) ------------
enum { EPI_BIAS = 0, EPI_RES = 1, EPI_GELU = 2 };

#define KCH         64
#define STAGE_BYTES 32768
#define NSTAGE      3
#define GSMEM_TOTAL (NSTAGE * STAGE_BYTES)

template <int EPI, typename OT>
__global__ __launch_bounds__(128, 2)
void gemm_f16(const __half* __restrict__ A, const __half* __restrict__ W,
              const float* __restrict__ bias, const float* __restrict__ res,
              OT* __restrict__ out, int K, int N) {
    extern __shared__ __align__(256) char smem_raw[];
    uint32_t sbase = smem_u32(smem_raw);

    int tid = threadIdx.x, w = tid >> 5, lane = tid & 31;
    int g = lane >> 2, t = lane & 3;
    int bm = blockIdx.y * 128, bn = blockIdx.x * 128;
    int wm = (w & 1) * 64, wn = (w >> 1) * 64;

    int j    = lane & 7;
    int bsel = lane >> 3;
    int rowA = wm + (bsel & 1) * 8 + j;
    int cA0  = bsel >> 1;
    int rowB = wn + (bsel >> 1) * 8 + j;
    int cB0  = bsel & 1;

    const int nk = K / KCH;

    auto load_stage = [&](int s, int k0) {
        uint32_t sb = sbase + s * STAGE_BYTES;
        #pragma unroll
        for (int i = 0; i < 16; i++) {
            int c = tid + 128 * i;
            int row = c >> 3, ch = c & 7;
            const __half* src = (row < 128)
                ? (A + (size_t)(bm + row) * K + k0 + ch * 8)
                : (W + (size_t)(bn + row - 128) * K + k0 + ch * 8);
            cpasync16(sb + row * 128 + 16 * (ch ^ (row & 7)), src);
        }
        asm volatile("cp.async.commit_group;" ::: "memory");
    };

    float acc[4][8][4];
    #pragma unroll
    for (int mt = 0; mt < 4; mt++)
        #pragma unroll
        for (int nt = 0; nt < 8; nt++)
            #pragma unroll
            for (int q = 0; q < 4; q++) acc[mt][nt][q] = 0.f;

    load_stage(0, 0);
    load_stage(1, KCH);

    for (int kt = 0; kt < nk; kt++) {
        asm volatile("cp.async.wait_group 1;" ::: "memory");  // stage kt ready
        __syncthreads();
        if (kt + 2 < nk) load_stage((kt + 2) % NSTAGE, (kt + 2) * KCH);
        else { asm volatile("cp.async.commit_group;" ::: "memory"); }

        uint32_t Asm = sbase + (kt % NSTAGE) * STAGE_BYTES;
        uint32_t Bsm = Asm + 16384;

        #pragma unroll
        for (int kb = 0; kb < 4; kb++) {
            uint32_t af[4][4];
            #pragma unroll
            for (int mt = 0; mt < 4; mt++) {
                int r = rowA + mt * 16;
                ldsm4(af[mt], Asm + r * 128 + 16 * ((2 * kb + cA0) ^ (r & 7)));
            }
            uint32_t bf[8][2];
            #pragma unroll
            for (int p = 0; p < 4; p++) {
                int n = rowB + p * 16;
                uint32_t tmp[4];
                ldsm4(tmp, Bsm + n * 128 + 16 * ((2 * kb + cB0) ^ (n & 7)));
                bf[2 * p][0]     = tmp[0]; bf[2 * p][1]     = tmp[1];
                bf[2 * p + 1][0] = tmp[2]; bf[2 * p + 1][1] = tmp[3];
            }
            #pragma unroll
            for (int mt = 0; mt < 4; mt++)
                #pragma unroll
                for (int nt = 0; nt < 8; nt++)
                    mma_f16(acc[mt][nt], af[mt], bf[nt]);
        }
        // stage (kt%3) reread-safe: next overwrite happens after iter kt+1's
        // top-of-loop barrier, which follows all reads here.
    }

    #pragma unroll
    for (int mt = 0; mt < 4; mt++) {
        #pragma unroll
        for (int nt = 0; nt < 8; nt++) {
            int rr0 = bm + wm + mt * 16 + g;
            int cc  = bn + wn + nt * 8 + 2 * t;
            float b0 = bias[cc], b1 = bias[cc + 1];
            #pragma unroll
            for (int hh = 0; hh < 2; hh++) {
                int rr = rr0 + hh * 8;
                float v0 = acc[mt][nt][hh * 2 + 0] + b0;
                float v1 = acc[mt][nt][hh * 2 + 1] + b1;
                if (EPI == EPI_RES) {
                    float2 rv = *(const float2*)(res + (size_t)rr * N + cc);
                    v0 += rv.x; v1 += rv.y;
                }
                if (EPI == EPI_GELU) {
                    v0 = gelu_tanh(v0);
                    v1 = gelu_tanh(v1);
                }
                OT* dst = out + (size_t)rr * N + cc;
                if (sizeof(OT) == 2) {
                    *(__half2*)dst = __floats2half2_rn(v0, v1);
                } else {
                    *(float2*)dst = make_float2(v0, v1);
                }
            }
        }
    }
}

// ---------------- Attention: fp16 mma flash-style (round 13, unchanged) -----
__global__ __launch_bounds__(160, 6)
void attn_mma(const __half* __restrict__ qkv, const float* __restrict__ abias,
              const float* __restrict__ bscale_p, __half* __restrict__ out) {
    __shared__ __align__(16) __half sK [80 * 64];
    __shared__ __align__(16) __half sV [80 * 64];
    __shared__ __align__(16) __half sQP[80 * 88];   // Q (first 64 cols), then P

    int bh = blockIdx.x, b = bh >> 4, h = bh & 15;
    int tid = threadIdx.x, w = tid >> 5, lane = tid & 31;
    int g = lane >> 2, t = lane & 3;
    size_t base = (size_t)b * SEQ * 3072 + (size_t)h * 64;

    for (int idx = tid; idx < 3 * 640; idx += 160) {
        int m = idx / 640, rem = idx - m * 640;
        int row = rem >> 3, ch = rem & 7;
        uint4 v = make_uint4(0, 0, 0, 0);
        if (row < SEQ)
            v = *(const uint4*)(qkv + base + (size_t)row * 3072 + m * 1024 + ch * 8);
        if (m == 0) {
            *(uint4*)(sQP + row * 88 + ch * 8) = v;
        } else {
            __half* dst = (m == 1) ? sK : sV;
            *(uint4*)(dst + row * 64 + ((ch ^ (row & 7)) * 8)) = v;
        }
    }
    __syncthreads();

    float bsc = *bscale_p;
    uint32_t sKb = smem_u32(sK), sVb = smem_u32(sV), sQPb = smem_u32(sQP);

    int j = lane & 7, bsel = lane >> 3;
    int mt = w;

    int rowA = mt * 16 + (bsel & 1) * 8 + j;
    int cA0  = bsel >> 1;
    uint32_t qa[4][4];
    #pragma unroll
    for (int kt = 0; kt < 4; kt++)
        ldsm4(qa[kt], sQPb + rowA * 176 + 16 * (2 * kt + cA0));

    float sacc[10][4];
    #pragma unroll
    for (int nt = 0; nt < 10; nt++)
        #pragma unroll
        for (int q = 0; q < 4; q++) sacc[nt][q] = 0.f;

    int rowKb = (bsel >> 1) * 8 + j;
    int cB0   = bsel & 1;
    #pragma unroll
    for (int nb = 0; nb < 5; nb++) {
        int rK = nb * 16 + rowKb;
        #pragma unroll
        for (int kt = 0; kt < 4; kt++) {
            uint32_t tmp[4];
            ldsm4(tmp, sKb + rK * 128 + 16 * ((2 * kt + cB0) ^ (rK & 7)));
            uint32_t bf0[2] = {tmp[0], tmp[1]}, bf1[2] = {tmp[2], tmp[3]};
            mma_f16(sacc[2 * nb],     qa[kt], bf0);
            mma_f16(sacc[2 * nb + 1], qa[kt], bf1);
        }
    }

    #pragma unroll
    for (int hr = 0; hr < 2; hr++) {
        int r = mt * 16 + g + 8 * hr;
        int rc = (r < SEQ) ? r : (SEQ - 1);
        const float* brow = abias + ((size_t)h * SEQ + rc) * SEQ;
        float l[20];
        float mx = -1e30f;
        #pragma unroll
        for (int nt = 0; nt < 10; nt++) {
            #pragma unroll
            for (int e = 0; e < 2; e++) {
                int c = 8 * nt + 2 * t + e;
                float lv = -1e30f;
                if (r < SEQ && c < SEQ)
                    lv = sacc[nt][2 * hr + e] * 0.125f + bsc * brow[c];
                l[nt * 2 + e] = lv;
                mx = fmaxf(mx, lv);
            }
        }
        mx = fmaxf(mx, __shfl_xor_sync(0xffffffffu, mx, 1));
        mx = fmaxf(mx, __shfl_xor_sync(0xffffffffu, mx, 2));
        float s = 0.f;
        #pragma unroll
        for (int i = 0; i < 20; i++) { l[i] = __expf(l[i] - mx); s += l[i]; }
        s += __shfl_xor_sync(0xffffffffu, s, 1);
        s += __shfl_xor_sync(0xffffffffu, s, 2);
        float inv = 1.0f / s;
        #pragma unroll
        for (int nt = 0; nt < 10; nt++)
            *(__half2*)(sQP + r * 88 + 8 * nt + 2 * t) =
                __floats2half2_rn(l[2 * nt] * inv, l[2 * nt + 1] * inv);
    }
    __syncwarp();

    float oacc[8][4];
    #pragma unroll
    for (int nt = 0; nt < 8; nt++)
        #pragma unroll
        for (int q = 0; q < 4; q++) oacc[nt][q] = 0.f;

    int rowP = mt * 16 + (bsel & 1) * 8 + j;
    int kl   = lane & 15;
    int ctop = lane >> 4;
    #pragma unroll
    for (int kt = 0; kt < 5; kt++) {
        uint32_t pa[4];
        ldsm4(pa, sQPb + rowP * 176 + 16 * (2 * kt + (bsel >> 1)));
        int krow = kt * 16 + kl;
        #pragma unroll
        for (int nb2 = 0; nb2 < 4; nb2++) {
            uint32_t tmp[4];
            int col8 = 2 * nb2 + ctop;
            ldsm4t(tmp, sVb + krow * 128 + 16 * (col8 ^ (krow & 7)));
            uint32_t bf0[2] = {tmp[0], tmp[1]}, bf1[2] = {tmp[2], tmp[3]};
            mma_f16(oacc[2 * nb2],     pa, bf0);
            mma_f16(oacc[2 * nb2 + 1], pa, bf1);
        }
    }

    size_t ob = (size_t)b * SEQ * 1024 + (size_t)h * 64;
    #pragma unroll
    for (int hr = 0; hr < 2; hr++) {
        int r = mt * 16 + g + 8 * hr;
        if (r < SEQ) {
            #pragma unroll
            for (int nt = 0; nt < 8; nt++)
                *(__half2*)(out + ob + (size_t)r * 1024 + 8 * nt + 2 * t) =
                    __floats2half2_rn(oacc[nt][2 * hr], oacc[nt][2 * hr + 1]);
        }
    }
}

// ---------------- launch -----------------------------------------------------
extern "C" void kernel_launch(void* const* d_in, const int* in_sizes, int n_in,
                              void* d_out, int out_size) {
    const float* x        = (const float*)d_in[0];
    const float* ln1_g    = (const float*)d_in[1];
    const float* ln1_b    = (const float*)d_in[2];
    const float* qkv_w    = (const float*)d_in[3];
    const float* qkv_b    = (const float*)d_in[4];
    const float* proj_w   = (const float*)d_in[5];
    const float* proj_b   = (const float*)d_in[6];
    const float* attnbias = (const float*)d_in[7];
    const float* bscale   = (const float*)d_in[8];
    const float* ln2_g    = (const float*)d_in[9];
    const float* ln2_b    = (const float*)d_in[10];
    const float* fc1_w    = (const float*)d_in[11];
    const float* fc1_b    = (const float*)d_in[12];
    const float* fc2_w    = (const float*)d_in[13];
    const float* fc2_b    = (const float*)d_in[14];
    float* out = (float*)d_out;

    __half *h, *qkv, *att, *act, *wq, *wp, *w1, *w2;
    cudaGetSymbolAddress((void**)&h,   g_h);
    cudaGetSymbolAddress((void**)&qkv, g_qkv);
    cudaGetSymbolAddress((void**)&att, g_att);
    cudaGetSymbolAddress((void**)&act, g_act);
    cudaGetSymbolAddress((void**)&wq,  g_wq);
    cudaGetSymbolAddress((void**)&wp,  g_wp);
    cudaGetSymbolAddress((void**)&w1,  g_w1);
    cudaGetSymbolAddress((void**)&w2,  g_w2);

    cudaFuncSetAttribute((const void*)gemm_f16<EPI_BIAS, __half>,
                         cudaFuncAttributeMaxDynamicSharedMemorySize, GSMEM_TOTAL);
    cudaFuncSetAttribute((const void*)gemm_f16<EPI_RES, float>,
                         cudaFuncAttributeMaxDynamicSharedMemorySize, GSMEM_TOTAL);
    cudaFuncSetAttribute((const void*)gemm_f16<EPI_GELU, __half>,
                         cudaFuncAttributeMaxDynamicSharedMemorySize, GSMEM_TOTAL);

    // 0. fp16 weights (single launch)
    conv_all<<<2048, 256>>>((const float2*)qkv_w, (const float2*)proj_w,
                            (const float2*)fc1_w, (const float2*)fc2_w,
                            (__half2*)wq, (__half2*)wp, (__half2*)w1, (__half2*)w2);

    // 1. h = LN1(x)   (fp16), warp-per-row
    ln_kernel<<<MTOT / 8, 256>>>(x, ln1_g, ln1_b, h);
    // 2. qkv = h @ qkv_w^T + qkv_b  (fp16 out)
    gemm_f16<EPI_BIAS, __half><<<dim3(3 * CC / 128, MTOT / 128), 128, GSMEM_TOTAL>>>(
        h, wq, qkv_b, nullptr, qkv, CC, 3 * CC);
    // 3. attention -> att (fp16), tensor-core path
    attn_mma<<<BB * HH, 160>>>(qkv, attnbias, bscale, att);
    // 4. out = x + att @ proj_w^T + proj_b  (fp32 out)
    gemm_f16<EPI_RES, float><<<dim3(CC / 128, MTOT / 128), 128, GSMEM_TOTAL>>>(
        att, wp, proj_b, x, out, CC, CC);
    // 5. h = LN2(out)  (fp16), warp-per-row
    ln_kernel<<<MTOT / 8, 256>>>(out, ln2_g, ln2_b, h);
    // 6. act = gelu(h @ fc1_w^T + fc1_b)  (fp16)
    gemm_f16<EPI_GELU, __half><<<dim3(HID / 128, MTOT / 128), 128, GSMEM_TOTAL>>>(
        h, w1, fc1_b, nullptr, act, CC, HID);
    // 7. out = out + act @ fc2_w^T + fc2_b  (fp32 out)
    gemm_f16<EPI_RES, float><<<dim3(CC / 128, MTOT / 128), 128, GSMEM_TOTAL>>>(
        act, w2, fc2_b, out, out, HID, CC);
}

// round 15
// speedup vs baseline: 1.0322x; 1.0007x over previous
#include <cuda_runtime.h>
#include <cuda_fp16.h>
#include <cstdint>
#include <math.h>

#define BB   1024
#define SEQ  65
#define CC   1024
#define HH   16
#define HID  4096
#define MTOT (BB*SEQ)   // 66560 = 520 * 128

// ---------------- scratch (device globals: no allocations allowed) ----------
__device__ __half g_h  [(size_t)MTOT * CC];      // LN output (fp16)
__device__ __half g_qkv[(size_t)MTOT * 3 * CC];  // QKV output (fp16)
__device__ __half g_att[(size_t)MTOT * CC];      // attention output (fp16)
__device__ __half g_act[(size_t)MTOT * HID];     // gelu(fc1) (fp16)
__device__ __half g_wq [(size_t)3 * CC * CC];    // fp16 weights
__device__ __half g_wp [(size_t)CC * CC];
__device__ __half g_w1 [(size_t)HID * CC];
__device__ __half g_w2 [(size_t)CC * HID];
__device__ float  g_biasp[HH * 80 * 80];         // pre-scaled padded attn bias

// ---------------- helpers ---------------------------------------------------
__device__ __forceinline__ void mma_f16(float c[4], const uint32_t a[4], const uint32_t b[2]) {
    asm volatile(
        "mma.sync.aligned.m16n8k16.row.col.f32.f16.f16.f32 "
        "{%0,%1,%2,%3}, {%4,%5,%6,%7}, {%8,%9}, {%0,%1,%2,%3};\n"
        : "+f"(c[0]), "+f"(c[1]), "+f"(c[2]), "+f"(c[3])
        : "r"(a[0]), "r"(a[1]), "r"(a[2]), "r"(a[3]), "r"(b[0]), "r"(b[1]));
}

__device__ __forceinline__ void ldsm4(uint32_t r[4], uint32_t addr) {
    asm volatile("ldmatrix.sync.aligned.m8n8.x4.shared.b16 {%0,%1,%2,%3}, [%4];"
        : "=r"(r[0]), "=r"(r[1]), "=r"(r[2]), "=r"(r[3]) : "r"(addr));
}

__device__ __forceinline__ void ldsm4t(uint32_t r[4], uint32_t addr) {
    asm volatile("ldmatrix.sync.aligned.m8n8.x4.trans.shared.b16 {%0,%1,%2,%3}, [%4];"
        : "=r"(r[0]), "=r"(r[1]), "=r"(r[2]), "=r"(r[3]) : "r"(addr));
}

__device__ __forceinline__ float gelu_tanh(float x) {
    float x3 = x * x * x;
    return 0.5f * x * (1.0f + tanhf(0.7978845608028654f * (x + 0.044715f * x3)));
}

__device__ __forceinline__ uint32_t smem_u32(const void* p) {
    uint32_t a;
    asm("{ .reg .u64 t; cvta.to.shared.u64 t, %1; cvt.u32.u64 %0, t; }" : "=r"(a) : "l"(p));
    return a;
}

__device__ __forceinline__ void cpasync16(uint32_t dst, const void* src) {
    asm volatile("cp.async.cg.shared.global [%0], [%1], 16;" :: "r"(dst), "l"(src));
}

// ---------------- fp32 -> fp16 conversion of ALL weights, one launch --------
#define NW_Q (3 * CC * CC / 2)
#define NW_P (CC * CC / 2)
#define NW_1 (HID * CC / 2)
#define NW_2 (CC * HID / 2)
#define NW_TOT (NW_Q + NW_P + NW_1 + NW_2)

__global__ __launch_bounds__(256)
void conv_all(const float2* __restrict__ sq, const float2* __restrict__ sp,
              const float2* __restrict__ s1, const float2* __restrict__ s2,
              __half2* __restrict__ dq, __half2* __restrict__ dp,
              __half2* __restrict__ d1, __half2* __restrict__ d2) {
    int i = blockIdx.x * blockDim.x + threadIdx.x;
    int stride = gridDim.x * blockDim.x;
    for (; i < NW_TOT; i += stride) {
        const float2* s; __half2* d; int off;
        if (i < NW_Q)                   { s = sq; d = dq; off = i; }
        else if (i < NW_Q + NW_P)       { s = sp; d = dp; off = i - NW_Q; }
        else if (i < NW_Q + NW_P + NW_1){ s = s1; d = d1; off = i - NW_Q - NW_P; }
        else                            { s = s2; d = d2; off = i - NW_Q - NW_P - NW_1; }
        float2 v = s[off];
        d[off] = __floats2half2_rn(v.x, v.y);
    }
}

// ---------------- bias prep: biasp[h][r][c] = bsc * abias[h][r][c], pad 0 ---
__global__ __launch_bounds__(256)
void bias_prep(const float* __restrict__ ab, const float* __restrict__ bscale_p,
               float* __restrict__ bp) {
    float bsc = *bscale_p;
    int i = blockIdx.x * 256 + threadIdx.x;
    if (i >= HH * 80 * 80) return;
    int c = i % 80, rem = i / 80;
    int r = rem % 80, h = rem / 80;
    float v = 0.f;
    if (r < SEQ && c < SEQ) v = bsc * ab[((size_t)h * SEQ + r) * SEQ + c];
    bp[i] = v;
}

// ---------------- LayerNorm: one WARP per row, 8 rows/block ------------------
__global__ __launch_bounds__(256)
void ln_kernel(const float* __restrict__ x, const float* __restrict__ g,
               const float* __restrict__ b, __half* __restrict__ y) {
    int wid  = threadIdx.x >> 5;
    int lane = threadIdx.x & 31;
    int row  = blockIdx.x * 8 + wid;

    const float4* xr = (const float4*)(x + (size_t)row * CC);
    float4 v[8];
    #pragma unroll
    for (int i = 0; i < 8; i++) v[i] = xr[lane + 32 * i];

    float s1 = 0.f, s2 = 0.f;
    #pragma unroll
    for (int i = 0; i < 8; i++) {
        s1 += v[i].x + v[i].y + v[i].z + v[i].w;
        s2 += v[i].x * v[i].x + v[i].y * v[i].y + v[i].z * v[i].z + v[i].w * v[i].w;
    }
    #pragma unroll
    for (int o = 16; o; o >>= 1) {
        s1 += __shfl_xor_sync(0xffffffffu, s1, o);
        s2 += __shfl_xor_sync(0xffffffffu, s2, o);
    }
    float mu  = s1 * (1.0f / CC);
    float var = s2 * (1.0f / CC) - mu * mu;
    float rs  = rsqrtf(var + 1e-5f);

    const float4* gr = (const float4*)g;
    const float4* br = (const float4*)b;
    __half2* yr = (__half2*)(y + (size_t)row * CC);
    #pragma unroll
    for (int i = 0; i < 8; i++) {
        int c4 = lane + 32 * i;
        float4 gv = gr[c4];
        float4 bv = br[c4];
        yr[2 * c4 + 0] = __floats2half2_rn((v[i].x - mu) * rs * gv.x + bv.x,
                                           (v[i].y - mu) * rs * gv.y + bv.y);
        yr[2 * c4 + 1] = __floats2half2_rn((v[i].z - mu) * rs * gv.z + bv.z,
                                           (v[i].w - mu) * rs * gv.w + bv.w);
    }
}

// ---------------- FP16 mma.sync GEMM (byte-exact round-7 config) ------------
enum { EPI_BIAS = 0, EPI_RES = 1, EPI_GELU = 2 };

#define KCH         64
#define STAGE_BYTES 32768
#define NSTAGE      3
#define GSMEM_TOTAL (NSTAGE * STAGE_BYTES)

template <int EPI, typename OT>
__global__ __launch_bounds__(128, 2)
void gemm_f16(const __half* __restrict__ A, const __half* __restrict__ W,
              const float* __restrict__ bias, const float* __restrict__ res,
              OT* __restrict__ out, int K, int N) {
    extern __shared__ __align__(256) char smem_raw[];
    uint32_t sbase = smem_u32(smem_raw);

    int tid = threadIdx.x, w = tid >> 5, lane = tid & 31;
    int g = lane >> 2, t = lane & 3;
    int bm = blockIdx.y * 128, bn = blockIdx.x * 128;
    int wm = (w & 1) * 64, wn = (w >> 1) * 64;

    int j    = lane & 7;
    int bsel = lane >> 3;
    int rowA = wm + (bsel & 1) * 8 + j;
    int cA0  = bsel >> 1;
    int rowB = wn + (bsel >> 1) * 8 + j;
    int cB0  = bsel & 1;

    const int nk = K / KCH;

    auto load_stage = [&](int s, int k0) {
        uint32_t sb = sbase + s * STAGE_BYTES;
        #pragma unroll
        for (int i = 0; i < 16; i++) {
            int c = tid + 128 * i;
            int row = c >> 3, ch = c & 7;
            const __half* src = (row < 128)
                ? (A + (size_t)(bm + row) * K + k0 + ch * 8)
                : (W + (size_t)(bn + row - 128) * K + k0 + ch * 8);
            cpasync16(sb + row * 128 + 16 * (ch ^ (row & 7)), src);
        }
        asm volatile("cp.async.commit_group;" ::: "memory");
    };

    float acc[4][8][4];
    #pragma unroll
    for (int mt = 0; mt < 4; mt++)
        #pragma unroll
        for (int nt = 0; nt < 8; nt++)
            #pragma unroll
            for (int q = 0; q < 4; q++) acc[mt][nt][q] = 0.f;

    load_stage(0, 0);
    load_stage(1, KCH);

    for (int kt = 0; kt < nk; kt++) {
        asm volatile("cp.async.wait_group 1;" ::: "memory");  // stage kt ready
        __syncthreads();
        if (kt + 2 < nk) load_stage((kt + 2) % NSTAGE, (kt + 2) * KCH);
        else { asm volatile("cp.async.commit_group;" ::: "memory"); }

        uint32_t Asm = sbase + (kt % NSTAGE) * STAGE_BYTES;
        uint32_t Bsm = Asm + 16384;

        #pragma unroll
        for (int kb = 0; kb < 4; kb++) {
            uint32_t af[4][4];
            #pragma unroll
            for (int mt = 0; mt < 4; mt++) {
                int r = rowA + mt * 16;
                ldsm4(af[mt], Asm + r * 128 + 16 * ((2 * kb + cA0) ^ (r & 7)));
            }
            uint32_t bf[8][2];
            #pragma unroll
            for (int p = 0; p < 4; p++) {
                int n = rowB + p * 16;
                uint32_t tmp[4];
                ldsm4(tmp, Bsm + n * 128 + 16 * ((2 * kb + cB0) ^ (n & 7)));
                bf[2 * p][0]     = tmp[0]; bf[2 * p][1]     = tmp[1];
                bf[2 * p + 1][0] = tmp[2]; bf[2 * p + 1][1] = tmp[3];
            }
            #pragma unroll
            for (int mt = 0; mt < 4; mt++)
                #pragma unroll
                for (int nt = 0; nt < 8; nt++)
                    mma_f16(acc[mt][nt], af[mt], bf[nt]);
        }
        // stage (kt%3) reread-safe: next overwrite happens after iter kt+1's
        // top-of-loop barrier, which follows all reads here.
    }

    #pragma unroll
    for (int mt = 0; mt < 4; mt++) {
        #pragma unroll
        for (int nt = 0; nt < 8; nt++) {
            int rr0 = bm + wm + mt * 16 + g;
            int cc  = bn + wn + nt * 8 + 2 * t;
            float b0 = bias[cc], b1 = bias[cc + 1];
            #pragma unroll
            for (int hh = 0; hh < 2; hh++) {
                int rr = rr0 + hh * 8;
                float v0 = acc[mt][nt][hh * 2 + 0] + b0;
                float v1 = acc[mt][nt][hh * 2 + 1] + b1;
                if (EPI == EPI_RES) {
                    float2 rv = *(const float2*)(res + (size_t)rr * N + cc);
                    v0 += rv.x; v1 += rv.y;
                }
                if (EPI == EPI_GELU) {
                    v0 = gelu_tanh(v0);
                    v1 = gelu_tanh(v1);
                }
                OT* dst = out + (size_t)rr * N + cc;
                if (sizeof(OT) == 2) {
                    *(__half2*)dst = __floats2half2_rn(v0, v1);
                } else {
                    *(float2*)dst = make_float2(v0, v1);
                }
            }
        }
    }
}

// ---------------- Attention: fp16 mma flash-style ---------------------------
// Round-13 structure; bias now read from pre-scaled padded table (stride 80,
// float2-aligned, no row clamp, unguarded vector loads).
__global__ __launch_bounds__(160, 6)
void attn_mma(const __half* __restrict__ qkv, const float* __restrict__ biasp,
              __half* __restrict__ out) {
    __shared__ __align__(16) __half sK [80 * 64];
    __shared__ __align__(16) __half sV [80 * 64];
    __shared__ __align__(16) __half sQP[80 * 88];   // Q (first 64 cols), then P

    int bh = blockIdx.x, b = bh >> 4, h = bh & 15;
    int tid = threadIdx.x, w = tid >> 5, lane = tid & 31;
    int g = lane >> 2, t = lane & 3;
    size_t base = (size_t)b * SEQ * 3072 + (size_t)h * 64;

    for (int idx = tid; idx < 3 * 640; idx += 160) {
        int m = idx / 640, rem = idx - m * 640;
        int row = rem >> 3, ch = rem & 7;
        uint4 v = make_uint4(0, 0, 0, 0);
        if (row < SEQ)
            v = *(const uint4*)(qkv + base + (size_t)row * 3072 + m * 1024 + ch * 8);
        if (m == 0) {
            *(uint4*)(sQP + row * 88 + ch * 8) = v;
        } else {
            __half* dst = (m == 1) ? sK : sV;
            *(uint4*)(dst + row * 64 + ((ch ^ (row & 7)) * 8)) = v;
        }
    }
    __syncthreads();

    uint32_t sKb = smem_u32(sK), sVb = smem_u32(sV), sQPb = smem_u32(sQP);

    int j = lane & 7, bsel = lane >> 3;
    int mt = w;

    int rowA = mt * 16 + (bsel & 1) * 8 + j;
    int cA0  = bsel >> 1;
    uint32_t qa[4][4];
    #pragma unroll
    for (int kt = 0; kt < 4; kt++)
        ldsm4(qa[kt], sQPb + rowA * 176 + 16 * (2 * kt + cA0));

    float sacc[10][4];
    #pragma unroll
    for (int nt = 0; nt < 10; nt++)
        #pragma unroll
        for (int q = 0; q < 4; q++) sacc[nt][q] = 0.f;

    int rowKb = (bsel >> 1) * 8 + j;
    int cB0   = bsel & 1;
    #pragma unroll
    for (int nb = 0; nb < 5; nb++) {
        int rK = nb * 16 + rowKb;
        #pragma unroll
        for (int kt = 0; kt < 4; kt++) {
            uint32_t tmp[4];
            ldsm4(tmp, sKb + rK * 128 + 16 * ((2 * kt + cB0) ^ (rK & 7)));
            uint32_t bf0[2] = {tmp[0], tmp[1]}, bf1[2] = {tmp[2], tmp[3]};
            mma_f16(sacc[2 * nb],     qa[kt], bf0);
            mma_f16(sacc[2 * nb + 1], qa[kt], bf1);
        }
    }

    // ---- softmax rows, write P (fp16) into sQP ----
    #pragma unroll
    for (int hr = 0; hr < 2; hr++) {
        int r = mt * 16 + g + 8 * hr;
        bool valid = (r < SEQ);
        const float* brow = biasp + ((size_t)h * 80 + r) * 80;
        float l[20];
        float mx = -1e30f;
        #pragma unroll
        for (int nt = 0; nt < 10; nt++) {
            float2 bv = *(const float2*)(brow + 8 * nt + 2 * t);
            #pragma unroll
            for (int e = 0; e < 2; e++) {
                int c = 8 * nt + 2 * t + e;
                float bval = (e == 0) ? bv.x : bv.y;
                float lv = -1e30f;
                if (valid && c < SEQ)
                    lv = sacc[nt][2 * hr + e] * 0.125f + bval;
                l[nt * 2 + e] = lv;
                mx = fmaxf(mx, lv);
            }
        }
        mx = fmaxf(mx, __shfl_xor_sync(0xffffffffu, mx, 1));
        mx = fmaxf(mx, __shfl_xor_sync(0xffffffffu, mx, 2));
        float s = 0.f;
        #pragma unroll
        for (int i = 0; i < 20; i++) { l[i] = __expf(l[i] - mx); s += l[i]; }
        s += __shfl_xor_sync(0xffffffffu, s, 1);
        s += __shfl_xor_sync(0xffffffffu, s, 2);
        float inv = 1.0f / s;
        #pragma unroll
        for (int nt = 0; nt < 10; nt++)
            *(__half2*)(sQP + r * 88 + 8 * nt + 2 * t) =
                __floats2half2_rn(l[2 * nt] * inv, l[2 * nt + 1] * inv);
    }
    __syncwarp();

    float oacc[8][4];
    #pragma unroll
    for (int nt = 0; nt < 8; nt++)
        #pragma unroll
        for (int q = 0; q < 4; q++) oacc[nt][q] = 0.f;

    int rowP = mt * 16 + (bsel & 1) * 8 + j;
    int kl   = lane & 15;
    int ctop = lane >> 4;
    #pragma unroll
    for (int kt = 0; kt < 5; kt++) {
        uint32_t pa[4];
        ldsm4(pa, sQPb + rowP * 176 + 16 * (2 * kt + (bsel >> 1)));
        int krow = kt * 16 + kl;
        #pragma unroll
        for (int nb2 = 0; nb2 < 4; nb2++) {
            uint32_t tmp[4];
            int col8 = 2 * nb2 + ctop;
            ldsm4t(tmp, sVb + krow * 128 + 16 * (col8 ^ (krow & 7)));
            uint32_t bf0[2] = {tmp[0], tmp[1]}, bf1[2] = {tmp[2], tmp[3]};
            mma_f16(oacc[2 * nb2],     pa, bf0);
            mma_f16(oacc[2 * nb2 + 1], pa, bf1);
        }
    }

    size_t ob = (size_t)b * SEQ * 1024 + (size_t)h * 64;
    #pragma unroll
    for (int hr = 0; hr < 2; hr++) {
        int r = mt * 16 + g + 8 * hr;
        if (r < SEQ) {
            #pragma unroll
            for (int nt = 0; nt < 8; nt++)
                *(__half2*)(out + ob + (size_t)r * 1024 + 8 * nt + 2 * t) =
                    __floats2half2_rn(oacc[nt][2 * hr], oacc[nt][2 * hr + 1]);
        }
    }
}

// ---------------- launch -----------------------------------------------------
extern "C" void kernel_launch(void* const* d_in, const int* in_sizes, int n_in,
                              void* d_out, int out_size) {
    const float* x        = (const float*)d_in[0];
    const float* ln1_g    = (const float*)d_in[1];
    const float* ln1_b    = (const float*)d_in[2];
    const float* qkv_w    = (const float*)d_in[3];
    const float* qkv_b    = (const float*)d_in[4];
    const float* proj_w   = (const float*)d_in[5];
    const float* proj_b   = (const float*)d_in[6];
    const float* attnbias = (const float*)d_in[7];
    const float* bscale   = (const float*)d_in[8];
    const float* ln2_g    = (const float*)d_in[9];
    const float* ln2_b    = (const float*)d_in[10];
    const float* fc1_w    = (const float*)d_in[11];
    const float* fc1_b    = (const float*)d_in[12];
    const float* fc2_w    = (const float*)d_in[13];
    const float* fc2_b    = (const float*)d_in[14];
    float* out = (float*)d_out;

    __half *h, *qkv, *att, *act, *wq, *wp, *w1, *w2;
    float* biasp;
    cudaGetSymbolAddress((void**)&h,   g_h);
    cudaGetSymbolAddress((void**)&qkv, g_qkv);
    cudaGetSymbolAddress((void**)&att, g_att);
    cudaGetSymbolAddress((void**)&act, g_act);
    cudaGetSymbolAddress((void**)&wq,  g_wq);
    cudaGetSymbolAddress((void**)&wp,  g_wp);
    cudaGetSymbolAddress((void**)&w1,  g_w1);
    cudaGetSymbolAddress((void**)&w2,  g_w2);
    cudaGetSymbolAddress((void**)&biasp, g_biasp);

    cudaFuncSetAttribute((const void*)gemm_f16<EPI_BIAS, __half>,
                         cudaFuncAttributeMaxDynamicSharedMemorySize, GSMEM_TOTAL);
    cudaFuncSetAttribute((const void*)gemm_f16<EPI_RES, float>,
                         cudaFuncAttributeMaxDynamicSharedMemorySize, GSMEM_TOTAL);
    cudaFuncSetAttribute((const void*)gemm_f16<EPI_GELU, __half>,
                         cudaFuncAttributeMaxDynamicSharedMemorySize, GSMEM_TOTAL);

    // 0. fp16 weights + bias table
    conv_all<<<2048, 256>>>((const float2*)qkv_w, (const float2*)proj_w,
                            (const float2*)fc1_w, (const float2*)fc2_w,
                            (__half2*)wq, (__half2*)wp, (__half2*)w1, (__half2*)w2);
    bias_prep<<<(HH * 80 * 80 + 255) / 256, 256>>>(attnbias, bscale, biasp);

    // 1. h = LN1(x)   (fp16), warp-per-row
    ln_kernel<<<MTOT / 8, 256>>>(x, ln1_g, ln1_b, h);
    // 2. qkv = h @ qkv_w^T + qkv_b  (fp16 out)
    gemm_f16<EPI_BIAS, __half><<<dim3(3 * CC / 128, MTOT / 128), 128, GSMEM_TOTAL>>>(
        h, wq, qkv_b, nullptr, qkv, CC, 3 * CC);
    // 3. attention -> att (fp16), tensor-core path
    attn_mma<<<BB * HH, 160>>>(qkv, biasp, att);
    // 4. out = x + att @ proj_w^T + proj_b  (fp32 out)
    gemm_f16<EPI_RES, float><<<dim3(CC / 128, MTOT / 128), 128, GSMEM_TOTAL>>>(
        att, wp, proj_b, x, out, CC, CC);
    // 5. h = LN2(out)  (fp16), warp-per-row
    ln_kernel<<<MTOT / 8, 256>>>(out, ln2_g, ln2_b, h);
    // 6. act = gelu(h @ fc1_w^T + fc1_b)  (fp16)
    gemm_f16<EPI_GELU, __half><<<dim3(HID / 128, MTOT / 128), 128, GSMEM_TOTAL>>>(
        h, w1, fc1_b, nullptr, act, CC, HID);
    // 7. out = out + act @ fc2_w^T + fc2_b  (fp32 out)
    gemm_f16<EPI_RES, float><<<dim3(CC / 128, MTOT / 128), 128, GSMEM_TOTAL>>>(
        act, w2, fc2_b, out, out, HID, CC);
}